// round 14
// baseline (speedup 1.0000x reference)
#include <cuda_runtime.h>
#include <cuda_bf16.h>
#include <math.h>
#include <stdint.h>

// Problem constants
#define BB 2
#define SS 2048
#define DIN 1024
#define HH 16
#define DKK 1024
#define DVV 1024
#define DOUT 1024
#define MROWS (BB*SS)          // 4096
#define BH (BB*HH)             // 32
#define HEADV 64
#define SCALE 0.125f
#define LN_EPS 1e-5f
#define NJC 8                  // j-chunks of 256

// Scratch
__device__ float g_res[(size_t)MROWS * DOUT];
__device__ float g_cbt[(size_t)BH * SS];
__device__ __nv_bfloat16 g_part[(size_t)BH * 16 * NJC * 128 * 64];  // 64 MB
__device__ float g_pm[(size_t)BH * 16 * NJC * 128];
__device__ float g_pl[(size_t)BH * 16 * NJC * 128];
__device__ __nv_bfloat16 g_qb[(size_t)MROWS * DKK];
__device__ __nv_bfloat16 g_kb[(size_t)MROWS * DKK];
__device__ __nv_bfloat16 g_vb[(size_t)MROWS * DVV];
__device__ __nv_bfloat16 g_xb[(size_t)MROWS * DIN];
__device__ __nv_bfloat16 g_wb[(size_t)4 * 1024 * 1024];
__device__ __nv_bfloat16 g_vt[(size_t)BH * HEADV * SS];
__device__ __nv_bfloat16 g_cxb[(size_t)MROWS * DVV];

// ======================= helpers ===========================================
__device__ __forceinline__ uint32_t smem_to_u32(const void* p) {
    uint32_t a;
    asm("{ .reg .u64 t; cvta.to.shared.u64 t, %1; cvt.u32.u64 %0, t; }" : "=r"(a) : "l"(p));
    return a;
}
__device__ __forceinline__ void cp16(uint32_t s, const void* g) {
    asm volatile("cp.async.cg.shared.global [%0], [%1], 16;" :: "r"(s), "l"(g));
}
#define CP_COMMIT() asm volatile("cp.async.commit_group;" ::: "memory")
#define CP_WAIT1()  asm volatile("cp.async.wait_group 1;" ::: "memory")
#define CP_WAIT0()  asm volatile("cp.async.wait_group 0;" ::: "memory")

__device__ __forceinline__ void ldsm_x4(uint32_t* r, uint32_t addr) {
    asm volatile("ldmatrix.sync.aligned.m8n8.x4.shared.b16 {%0,%1,%2,%3}, [%4];"
        : "=r"(r[0]), "=r"(r[1]), "=r"(r[2]), "=r"(r[3]) : "r"(addr));
}
__device__ __forceinline__ void ldsm_x2(uint32_t* r, uint32_t addr) {
    asm volatile("ldmatrix.sync.aligned.m8n8.x2.shared.b16 {%0,%1}, [%2];"
        : "=r"(r[0]), "=r"(r[1]) : "r"(addr));
}
__device__ __forceinline__ void mma_bf16(float* c, const uint32_t* a, const uint32_t* b) {
    asm volatile("mma.sync.aligned.m16n8k16.row.col.f32.bf16.bf16.f32 "
        "{%0,%1,%2,%3}, {%4,%5,%6,%7}, {%8,%9}, {%0,%1,%2,%3};"
        : "+f"(c[0]), "+f"(c[1]), "+f"(c[2]), "+f"(c[3])
        : "r"(a[0]), "r"(a[1]), "r"(a[2]), "r"(a[3]), "r"(b[0]), "r"(b[1]));
}
__device__ __forceinline__ uint32_t pack2(__nv_bfloat16 a, __nv_bfloat16 b) {
    return (uint32_t)__bfloat16_as_ushort(a) | ((uint32_t)__bfloat16_as_ushort(b) << 16);
}
__device__ __forceinline__ float2 bf2_to_f2(uint32_t u) {
    float2 r;
    r.x = __bfloat162float(__ushort_as_bfloat16((unsigned short)(u & 0xffffu)));
    r.y = __bfloat162float(__ushort_as_bfloat16((unsigned short)(u >> 16)));
    return r;
}

// ======================= fp32 -> bf16 convert ==============================
__global__ __launch_bounds__(256)
void cvt_bf_kernel(const float* __restrict__ in, __nv_bfloat16* __restrict__ o)
{
    const size_t i4 = (size_t)blockIdx.x * 256 + threadIdx.x;
    float4 v = *(const float4*)(in + i4 * 4);
    uint2 p;
    p.x = pack2(__float2bfloat16(v.x), __float2bfloat16(v.y));
    p.y = pack2(__float2bfloat16(v.z), __float2bfloat16(v.w));
    *(uint2*)(o + i4 * 4) = p;
}

// ======================= content bias (direct to cbt) ======================
__global__ __launch_bounds__(256)
void cb_kernel(const float* __restrict__ x, const float* __restrict__ Wcb,
               float* __restrict__ cbt)
{
    __shared__ float xs[16][132];
    const int tid = threadIdx.x;
    const int r = tid >> 4;
    const int h = tid & 15;
    const int row0 = blockIdx.x * 16;

    float acc = 0.f;
    for (int c0 = 0; c0 < DIN; c0 += 128) {
        __syncthreads();
#pragma unroll
        for (int i = 0; i < 2; i++) {
            const int id = tid + i * 256;
            const int rr = id >> 5, cc = (id & 31) * 4;
            *(float4*)&xs[rr][cc] = *(const float4*)(x + (size_t)(row0 + rr) * DIN + c0 + cc);
        }
        __syncthreads();
        const float4* wp = (const float4*)(Wcb + (size_t)h * DIN + c0);
#pragma unroll
        for (int i = 0; i < 32; i++) {
            float4 w = wp[i];
            float4 xv = *(const float4*)&xs[r][i * 4];
            acc += xv.x * w.x + xv.y * w.y + xv.z * w.z + xv.w * w.w;
        }
    }
    const int row = row0 + r;
    const int b = row >> 11, s = row & 2047;
    cbt[((size_t)(b * HH + h)) * SS + s] = acc * SCALE;
}

// ======================= 1-pass HMMA NT GEMM, fp32 out (out proj) ==========
#define P1_A 0
#define P1_B 16384
#define P1_STAGE 32768
#define P1_NST 16

__global__ __launch_bounds__(256)
void hmma1_nt_kernel(const __nv_bfloat16* __restrict__ Ap, const __nv_bfloat16* __restrict__ Bp,
                     const float* __restrict__ bias, const float* __restrict__ resid,
                     float* __restrict__ C, int N)
{
    extern __shared__ __align__(1024) char smem[];
    const uint32_t sb = smem_to_u32(smem);

    const int tid = threadIdx.x;
    const int wid = tid >> 5;
    const int lane = tid & 31;
    const int m0 = blockIdx.y * 128;
    const int n0 = blockIdx.x * 128;
    const int warp_m = wid >> 2;
    const int warp_n = wid & 3;

    const __nv_bfloat16* A_b = Ap + (size_t)m0 * DKK;
    const __nv_bfloat16* B_b = Bp + (size_t)n0 * DKK;

    float acc[4][4][4];
#pragma unroll
    for (int mt = 0; mt < 4; mt++)
#pragma unroll
        for (int nt = 0; nt < 4; nt++)
#pragma unroll
            for (int e = 0; e < 4; e++) acc[mt][nt][e] = 0.f;

    int cso[4];
    size_t cgi[4];
#pragma unroll
    for (int r = 0; r < 4; r++) {
        const int chunk = tid + 256 * r;
        const int row = chunk >> 3;
        const int cc = chunk & 7;
        cso[r] = row * 128 + ((cc * 16) ^ ((row & 7) << 4));
        cgi[r] = (size_t)row * DKK + cc * 8;
    }

    const int rowA = warp_m * 64 + (lane & 15);
    const int colA = ((lane >> 4) << 4);
    const uint32_t maskA = (rowA & 7) << 4;
    const int rowB = warp_n * 32 + (lane & 7);
    const int colB = ((lane >> 3) & 1) << 4;
    const uint32_t maskB = (rowB & 7) << 4;

    {
        const uint32_t st = sb;
#pragma unroll
        for (int r = 0; r < 4; r++) {
            cp16(st + P1_A + cso[r], A_b + cgi[r]);
            cp16(st + P1_B + cso[r], B_b + cgi[r]);
        }
        CP_COMMIT();
    }

    for (int s = 0; s < P1_NST; s++) {
        if (s + 1 < P1_NST) {
            const uint32_t st = sb + ((s + 1) & 1) * P1_STAGE;
            const size_t koff = (size_t)(s + 1) * 64;
#pragma unroll
            for (int r = 0; r < 4; r++) {
                cp16(st + P1_A + cso[r], A_b + cgi[r] + koff);
                cp16(st + P1_B + cso[r], B_b + cgi[r] + koff);
            }
            CP_COMMIT();
            CP_WAIT1();
        } else {
            CP_WAIT0();
        }
        __syncthreads();

        const uint32_t st = sb + (s & 1) * P1_STAGE;
#pragma unroll
        for (int ks = 0; ks < 4; ks++) {
            const int k0b = ks * 32;
            uint32_t Af[4][4], Bf[4][2];
#pragma unroll
            for (int mt = 0; mt < 4; mt++)
                ldsm_x4(Af[mt], st + P1_A + (uint32_t)((rowA + mt * 16) * 128) + (uint32_t)((k0b + colA) ^ maskA));
#pragma unroll
            for (int nt = 0; nt < 4; nt++)
                ldsm_x2(Bf[nt], st + P1_B + (uint32_t)((rowB + nt * 8) * 128) + (uint32_t)((k0b + colB) ^ maskB));
#pragma unroll
            for (int mt = 0; mt < 4; mt++)
#pragma unroll
                for (int nt = 0; nt < 4; nt++)
                    mma_bf16(acc[mt][nt], Af[mt], Bf[nt]);
        }
        __syncthreads();
    }

    const int r0 = lane >> 2;
    const int c0 = (lane & 3) * 2;
#pragma unroll
    for (int mt = 0; mt < 4; mt++) {
        const int mrow = m0 + warp_m * 64 + mt * 16 + r0;
#pragma unroll
        for (int nt = 0; nt < 4; nt++) {
            const int ncol = n0 + warp_n * 32 + nt * 8 + c0;
#pragma unroll
            for (int half = 0; half < 2; half++) {
                const int m = mrow + half * 8;
                float2 v = half ? make_float2(acc[mt][nt][2], acc[mt][nt][3])
                                : make_float2(acc[mt][nt][0], acc[mt][nt][1]);
                if (bias)  { v.x += bias[ncol]; v.y += bias[ncol + 1]; }
                if (resid) {
                    float2 rr = *(const float2*)(resid + (size_t)m * N + ncol);
                    v.x += rr.x; v.y += rr.y;
                }
                *(float2*)(C + (size_t)m * N + ncol) = v;
            }
        }
    }
}

// ======================= 1-pass HMMA NT GEMM, bf16 out (q/k/v proj) ========
__global__ __launch_bounds__(256)
void hmma1b_nt_kernel(const __nv_bfloat16* __restrict__ Ap, const __nv_bfloat16* __restrict__ Bp,
                      const float* __restrict__ bias, __nv_bfloat16* __restrict__ C, int N)
{
    extern __shared__ __align__(1024) char smem[];
    const uint32_t sb = smem_to_u32(smem);

    const int tid = threadIdx.x;
    const int wid = tid >> 5;
    const int lane = tid & 31;
    const int m0 = blockIdx.y * 128;
    const int n0 = blockIdx.x * 128;
    const int warp_m = wid >> 2;
    const int warp_n = wid & 3;

    const __nv_bfloat16* A_b = Ap + (size_t)m0 * DKK;
    const __nv_bfloat16* B_b = Bp + (size_t)n0 * DKK;

    float acc[4][4][4];
#pragma unroll
    for (int mt = 0; mt < 4; mt++)
#pragma unroll
        for (int nt = 0; nt < 4; nt++)
#pragma unroll
            for (int e = 0; e < 4; e++) acc[mt][nt][e] = 0.f;

    int cso[4];
    size_t cgi[4];
#pragma unroll
    for (int r = 0; r < 4; r++) {
        const int chunk = tid + 256 * r;
        const int row = chunk >> 3;
        const int cc = chunk & 7;
        cso[r] = row * 128 + ((cc * 16) ^ ((row & 7) << 4));
        cgi[r] = (size_t)row * DKK + cc * 8;
    }

    const int rowA = warp_m * 64 + (lane & 15);
    const int colA = ((lane >> 4) << 4);
    const uint32_t maskA = (rowA & 7) << 4;
    const int rowB = warp_n * 32 + (lane & 7);
    const int colB = ((lane >> 3) & 1) << 4;
    const uint32_t maskB = (rowB & 7) << 4;

    {
        const uint32_t st = sb;
#pragma unroll
        for (int r = 0; r < 4; r++) {
            cp16(st + P1_A + cso[r], A_b + cgi[r]);
            cp16(st + P1_B + cso[r], B_b + cgi[r]);
        }
        CP_COMMIT();
    }

    for (int s = 0; s < P1_NST; s++) {
        if (s + 1 < P1_NST) {
            const uint32_t st = sb + ((s + 1) & 1) * P1_STAGE;
            const size_t koff = (size_t)(s + 1) * 64;
#pragma unroll
            for (int r = 0; r < 4; r++) {
                cp16(st + P1_A + cso[r], A_b + cgi[r] + koff);
                cp16(st + P1_B + cso[r], B_b + cgi[r] + koff);
            }
            CP_COMMIT();
            CP_WAIT1();
        } else {
            CP_WAIT0();
        }
        __syncthreads();

        const uint32_t st = sb + (s & 1) * P1_STAGE;
#pragma unroll
        for (int ks = 0; ks < 4; ks++) {
            const int k0b = ks * 32;
            uint32_t Af[4][4], Bf[4][2];
#pragma unroll
            for (int mt = 0; mt < 4; mt++)
                ldsm_x4(Af[mt], st + P1_A + (uint32_t)((rowA + mt * 16) * 128) + (uint32_t)((k0b + colA) ^ maskA));
#pragma unroll
            for (int nt = 0; nt < 4; nt++)
                ldsm_x2(Bf[nt], st + P1_B + (uint32_t)((rowB + nt * 8) * 128) + (uint32_t)((k0b + colB) ^ maskB));
#pragma unroll
            for (int mt = 0; mt < 4; mt++)
#pragma unroll
                for (int nt = 0; nt < 4; nt++)
                    mma_bf16(acc[mt][nt], Af[mt], Bf[nt]);
        }
        __syncthreads();
    }

    const int r0 = lane >> 2;
    const int c0 = (lane & 3) * 2;
#pragma unroll
    for (int mt = 0; mt < 4; mt++) {
        const int mrow = m0 + warp_m * 64 + mt * 16 + r0;
#pragma unroll
        for (int nt = 0; nt < 4; nt++) {
            const int ncol = n0 + warp_n * 32 + nt * 8 + c0;
            float b0 = 0.f, b1 = 0.f;
            if (bias) { b0 = bias[ncol]; b1 = bias[ncol + 1]; }
#pragma unroll
            for (int half = 0; half < 2; half++) {
                const int m = mrow + half * 8;
                float vx = (half ? acc[mt][nt][2] : acc[mt][nt][0]) + b0;
                float vy = (half ? acc[mt][nt][3] : acc[mt][nt][1]) + b1;
                *(uint32_t*)(C + (size_t)m * N + ncol) =
                    pack2(__float2bfloat16(vx), __float2bfloat16(vy));
            }
        }
    }
}

// ======================= prep V^T per head (bf16 in) =======================
__global__ __launch_bounds__(256)
void prep_vt_kernel(const __nv_bfloat16* __restrict__ v, __nv_bfloat16* __restrict__ vt)
{
    const int tid = threadIdx.x;
    const int bh = blockIdx.z;
    const int b = bh >> 4, h = bh & 15;
    const int j = blockIdx.x * 64 + (tid & 63);
    const int vvg = blockIdx.y * 4 + (tid >> 6);
    uint2 v4 = *(const uint2*)(v + ((size_t)b * SS + j) * DVV + h * HEADV + vvg * 4);
    __nv_bfloat16 e0 = __ushort_as_bfloat16((unsigned short)(v4.x & 0xffffu));
    __nv_bfloat16 e1 = __ushort_as_bfloat16((unsigned short)(v4.x >> 16));
    __nv_bfloat16 e2 = __ushort_as_bfloat16((unsigned short)(v4.y & 0xffffu));
    __nv_bfloat16 e3 = __ushort_as_bfloat16((unsigned short)(v4.y >> 16));
    const size_t ob = ((size_t)bh * HEADV + vvg * 4) * SS + j;
    vt[ob + 0 * SS] = e0;
    vt[ob + 1 * SS] = e1;
    vt[ob + 2 * SS] = e2;
    vt[ob + 3 * SS] = e3;
}

// ======================= phase 1: QK (mix folded) + softmax + PV ===========
#define SC_A  0
#define SC_B  16384
#define SC_STAGE 49152
#define SC_NST 16
#define FL_P   0
#define FL_V   65536
#define FL_STAT 98304
#define FL_M    100352
#define FL_L    100864
#define FL_MIX  101376          // mixing bf16x2: DKK/2 uint32 = 2 KB
#define FL_SMEM 103424

__global__ __launch_bounds__(256, 1)
void flash1_kernel(const __nv_bfloat16* __restrict__ qb, const __nv_bfloat16* __restrict__ kb,
                   const float* __restrict__ mixing, const float* __restrict__ cbt,
                   const __nv_bfloat16* __restrict__ vt,
                   __nv_bfloat16* __restrict__ part, float* __restrict__ pm, float* __restrict__ pl)
{
    extern __shared__ __align__(1024) char smem[];
    const uint32_t sb = smem_to_u32(smem);
    float* sm_stat = (float*)(smem + FL_STAT);
    float* sm_m    = (float*)(smem + FL_M);
    float* sm_l    = (float*)(smem + FL_L);

    const int tid = threadIdx.x;
    const int wid = tid >> 5;
    const int lane = tid & 31;
    const int jc = blockIdx.x;
    const int iblk = blockIdx.y;
    const int bh = blockIdx.z;
    const int b = bh >> 4, h = bh & 15;
    const int i0 = iblk * 128;
    const int j0 = jc * 256;
    const int warp_m = wid >> 2;
    const int warp_n = wid & 3;

    const __nv_bfloat16* qb_b = qb + ((size_t)b * SS + i0) * DKK;   // shared across heads
    const __nv_bfloat16* kb_b = kb + ((size_t)b * SS + j0) * DKK;

    // mixing (bf16x2, *SCALE) into smem
    for (int t = tid; t < DKK / 2; t += 256) {
        float2 mv = *(const float2*)(mixing + (size_t)h * DKK + t * 2);
        ((uint32_t*)(smem + FL_MIX))[t] =
            pack2(__float2bfloat16(mv.x * SCALE), __float2bfloat16(mv.y * SCALE));
    }

    float acc[4][8][4];
#pragma unroll
    for (int mt = 0; mt < 4; mt++)
#pragma unroll
        for (int nn = 0; nn < 8; nn++)
#pragma unroll
            for (int e = 0; e < 4; e++) acc[mt][nn][e] = 0.f;

    int csoA[4];  size_t cgiA[4];
#pragma unroll
    for (int r = 0; r < 4; r++) {
        const int chunk = tid + 256 * r;
        const int row = chunk >> 3, cc = chunk & 7;
        csoA[r] = row * 128 + ((cc * 16) ^ ((row & 7) << 4));
        cgiA[r] = (size_t)row * DKK + cc * 8;
    }
    int csoB[8];  size_t cgiB[8];
#pragma unroll
    for (int r = 0; r < 8; r++) {
        const int chunk = tid + 256 * r;
        const int row = chunk >> 3, cc = chunk & 7;
        csoB[r] = row * 128 + ((cc * 16) ^ ((row & 7) << 4));
        cgiB[r] = (size_t)row * DKK + cc * 8;
    }

    // ---- QK^T mainloop -----------------------------------------------------
    {
        const uint32_t st = sb;
#pragma unroll
        for (int r = 0; r < 4; r++)
            cp16(st + SC_A + csoA[r], qb_b + cgiA[r]);
#pragma unroll
        for (int r = 0; r < 8; r++)
            cp16(st + SC_B + csoB[r], kb_b + cgiB[r]);
        CP_COMMIT();
    }

    for (int s = 0; s < SC_NST; s++) {
        if (s + 1 < SC_NST) {
            const uint32_t st = sb + ((s + 1) & 1) * SC_STAGE;
            const size_t koff = (size_t)(s + 1) * 64;
#pragma unroll
            for (int r = 0; r < 4; r++)
                cp16(st + SC_A + csoA[r], qb_b + cgiA[r] + koff);
#pragma unroll
            for (int r = 0; r < 8; r++)
                cp16(st + SC_B + csoB[r], kb_b + cgiB[r] + koff);
            CP_COMMIT();
            CP_WAIT1();
        } else {
            CP_WAIT0();
        }
        __syncthreads();

        // in-place scale of A tile by mixing (bf16x2): chunk cc holds cols cc*8..cc*8+7
        {
            char* stp = smem + (s & 1) * SC_STAGE;
            const __nv_bfloat162* mz = (const __nv_bfloat162*)(smem + FL_MIX) + s * 32;
#pragma unroll
            for (int r = 0; r < 4; r++) {
                const int cc = (tid + 256 * r) & 7;
                uint4 v = *(uint4*)(stp + SC_A + csoA[r]);
                __nv_bfloat162* ve = (__nv_bfloat162*)&v;
                const __nv_bfloat162* mp = mz + cc * 4;
                ve[0] = __hmul2(ve[0], mp[0]);
                ve[1] = __hmul2(ve[1], mp[1]);
                ve[2] = __hmul2(ve[2], mp[2]);
                ve[3] = __hmul2(ve[3], mp[3]);
                *(uint4*)(stp + SC_A + csoA[r]) = v;
            }
        }
        __syncthreads();

        const uint32_t st = sb + (s & 1) * SC_STAGE;
#pragma unroll
        for (int ks = 0; ks < 4; ks++) {
            const int k0b = ks * 32;
            uint32_t Af[4][4];
#pragma unroll
            for (int mt = 0; mt < 4; mt++) {
                const int rowA = warp_m * 64 + mt * 16 + (lane & 15);
                const uint32_t cA = (uint32_t)((k0b + ((lane >> 4) << 4)) ^ ((rowA & 7) << 4));
                ldsm_x4(Af[mt], st + SC_A + (uint32_t)(rowA * 128) + cA);
            }
#pragma unroll
            for (int ng = 0; ng < 4; ng++) {
                const int rowB = warp_n * 64 + ng * 16 + (lane & 7) + ((lane & 16) >> 1);
                const uint32_t cB = (uint32_t)((k0b + (((lane >> 3) & 1) << 4)) ^ ((rowB & 7) << 4));
                uint32_t B4[4];
                ldsm_x4(B4, st + SC_B + (uint32_t)(rowB * 128) + cB);
#pragma unroll
                for (int mt = 0; mt < 4; mt++) {
                    mma_bf16(acc[mt][ng * 2 + 0], Af[mt], B4 + 0);
                    mma_bf16(acc[mt][ng * 2 + 1], Af[mt], B4 + 2);
                }
            }
        }
        __syncthreads();
    }

    // ---- V prefetch into freed stage smem ----------------------------------
#pragma unroll
    for (int c = 0; c < 2; c++) {
#pragma unroll
        for (int r = 0; r < 4; r++) {
            const int id = tid + 256 * r;
            const int row = id >> 4, cc = id & 15;
            const uint32_t so = (uint32_t)(row * 256 + ((cc * 16) ^ ((row & 7) << 4)));
            const size_t gi = ((size_t)bh * HEADV + row) * SS + j0 + c * 128 + cc * 8;
            cp16(sb + FL_V + c * 16384 + so, vt + gi);
        }
    }
    CP_COMMIT();

    // ---- add content bias, row max ----------------------------------------
    const float* cbp = cbt + (size_t)bh * SS + j0;
    float rmax[8];
#pragma unroll
    for (int i = 0; i < 8; i++) rmax[i] = -INFINITY;
#pragma unroll
    for (int nn = 0; nn < 8; nn++) {
        float2 cb2 = *(const float2*)(cbp + warp_n * 64 + nn * 8 + (lane & 3) * 2);
#pragma unroll
        for (int mt = 0; mt < 4; mt++) {
            acc[mt][nn][0] += cb2.x; acc[mt][nn][1] += cb2.y;
            acc[mt][nn][2] += cb2.x; acc[mt][nn][3] += cb2.y;
            rmax[mt * 2 + 0] = fmaxf(rmax[mt * 2 + 0], fmaxf(acc[mt][nn][0], acc[mt][nn][1]));
            rmax[mt * 2 + 1] = fmaxf(rmax[mt * 2 + 1], fmaxf(acc[mt][nn][2], acc[mt][nn][3]));
        }
    }
#pragma unroll
    for (int i = 0; i < 8; i++) {
        rmax[i] = fmaxf(rmax[i], __shfl_xor_sync(0xffffffffu, rmax[i], 1));
        rmax[i] = fmaxf(rmax[i], __shfl_xor_sync(0xffffffffu, rmax[i], 2));
    }
    if ((lane & 3) == 0) {
#pragma unroll
        for (int mt = 0; mt < 4; mt++) {
            const int r = warp_m * 64 + mt * 16 + (lane >> 2);
            sm_stat[(r + 0) * 4 + warp_n] = rmax[mt * 2 + 0];
            sm_stat[(r + 8) * 4 + warp_n] = rmax[mt * 2 + 1];
        }
    }
    __syncthreads();
    if (tid < 128) {
        sm_m[tid] = fmaxf(fmaxf(sm_stat[tid * 4 + 0], sm_stat[tid * 4 + 1]),
                          fmaxf(sm_stat[tid * 4 + 2], sm_stat[tid * 4 + 3]));
    }
    __syncthreads();

    // ---- exp, P store (512B pitch), partial sums --------------------------
    float rsum[8];
#pragma unroll
    for (int i = 0; i < 8; i++) rsum[i] = 0.f;
#pragma unroll
    for (int mt = 0; mt < 4; mt++) {
        const int r0 = warp_m * 64 + mt * 16 + (lane >> 2);
        const float mn0 = sm_m[r0];
        const float mn1 = sm_m[r0 + 8];
        const uint32_t off0base = (uint32_t)(r0 * 512);
        const uint32_t off1base = (uint32_t)((r0 + 8) * 512);
        const uint32_t mask0 = (uint32_t)((r0 & 7) << 4);
        const uint32_t mask1 = (uint32_t)(((r0 + 8) & 7) << 4);
#pragma unroll
        for (int nn = 0; nn < 8; nn++) {
            float p0 = __expf(acc[mt][nn][0] - mn0);
            float p1 = __expf(acc[mt][nn][1] - mn0);
            float p2 = __expf(acc[mt][nn][2] - mn1);
            float p3 = __expf(acc[mt][nn][3] - mn1);
            rsum[mt * 2 + 0] += p0 + p1;
            rsum[mt * 2 + 1] += p2 + p3;
            const uint32_t colbyte = (uint32_t)((warp_n * 64 + nn * 8 + (lane & 3) * 2) * 2);
            *(uint32_t*)(smem + FL_P + off0base + (colbyte ^ mask0)) = pack2(__float2bfloat16(p0), __float2bfloat16(p1));
            *(uint32_t*)(smem + FL_P + off1base + (colbyte ^ mask1)) = pack2(__float2bfloat16(p2), __float2bfloat16(p3));
        }
    }
#pragma unroll
    for (int i = 0; i < 8; i++) {
        rsum[i] += __shfl_xor_sync(0xffffffffu, rsum[i], 1);
        rsum[i] += __shfl_xor_sync(0xffffffffu, rsum[i], 2);
    }
    if ((lane & 3) == 0) {
#pragma unroll
        for (int mt = 0; mt < 4; mt++) {
            const int r = warp_m * 64 + mt * 16 + (lane >> 2);
            sm_stat[(r + 0) * 4 + warp_n] = rsum[mt * 2 + 0];
            sm_stat[(r + 8) * 4 + warp_n] = rsum[mt * 2 + 1];
        }
    }
    __syncthreads();
    if (tid < 128) {
        sm_l[tid] = sm_stat[tid * 4 + 0] + sm_stat[tid * 4 + 1]
                  + sm_stat[tid * 4 + 2] + sm_stat[tid * 4 + 3];
    }
    CP_WAIT0();
    __syncthreads();

    // ---- PV: O = P(128x256) @ V^T ------------------------------------------
    float O[8][4];
#pragma unroll
    for (int nn = 0; nn < 8; nn++)
#pragma unroll
        for (int e = 0; e < 4; e++) O[nn][e] = 0.f;

    const int m0w = wid * 16;
#pragma unroll
    for (int ks = 0; ks < 16; ks++) {
        const int chunk = ks >> 3;
        const int k0b = (ks & 7) * 32;
        uint32_t P4[4];
        const int rowa = m0w + (lane & 15);
        const uint32_t cA = (uint32_t)((ks * 32 + ((lane >> 4) << 4)) ^ ((rowa & 7) << 4));
        ldsm_x4(P4, sb + FL_P + (uint32_t)(rowa * 512) + cA);
        const uint32_t vbase = sb + FL_V + chunk * 16384;
#pragma unroll
        for (int ng = 0; ng < 4; ng++) {
            const int rowb = ng * 16 + (lane & 7) + ((lane & 16) >> 1);
            const uint32_t cB = (uint32_t)((k0b + (((lane >> 3) & 1) << 4)) ^ ((rowb & 7) << 4));
            uint32_t V4[4];
            ldsm_x4(V4, vbase + (uint32_t)(rowb * 256) + cB);
            mma_bf16(O[ng * 2 + 0], P4, V4 + 0);
            mma_bf16(O[ng * 2 + 1], P4, V4 + 2);
        }
    }

    // ---- write partial O (bf16) + stats ------------------------------------
    const size_t slot = ((size_t)bh * 16 + iblk) * NJC + jc;
    __nv_bfloat16* pbase = part + slot * (128 * 64);
    const int r0 = m0w + (lane >> 2);
    const int r1 = r0 + 8;
    const int c0 = (lane & 3) * 2;
#pragma unroll
    for (int nn = 0; nn < 8; nn++) {
        const int col = nn * 8 + c0;
        *(uint32_t*)(pbase + (size_t)r0 * 64 + col) = pack2(__float2bfloat16(O[nn][0]), __float2bfloat16(O[nn][1]));
        *(uint32_t*)(pbase + (size_t)r1 * 64 + col) = pack2(__float2bfloat16(O[nn][2]), __float2bfloat16(O[nn][3]));
    }
    if (tid < 128) {
        pm[slot * 128 + tid] = sm_m[tid];
        pl[slot * 128 + tid] = sm_l[tid];
    }
}

// ======================= phase 2: combine partials =========================
__global__ __launch_bounds__(256)
void combine_kernel(const __nv_bfloat16* __restrict__ part, const float* __restrict__ pm,
                    const float* __restrict__ pl, __nv_bfloat16* __restrict__ cxb)
{
    const int tid = threadIdx.x;
    const int iblk = blockIdx.x;
    const int bh = blockIdx.y;
    const int b = bh >> 4, h = bh & 15;
    const int row = tid >> 1;
    const int colh = (tid & 1) * 32;

    const size_t slot0 = ((size_t)bh * 16 + iblk) * NJC;

    float mj[NJC], w[NJC];
    float m = -INFINITY;
#pragma unroll
    for (int j = 0; j < NJC; j++) {
        mj[j] = pm[(slot0 + j) * 128 + row];
        m = fmaxf(m, mj[j]);
    }
    float lsum = 0.f;
#pragma unroll
    for (int j = 0; j < NJC; j++) {
        w[j] = __expf(mj[j] - m);
        lsum += pl[(slot0 + j) * 128 + row] * w[j];
    }
    const float inv = 1.f / lsum;

    float o[32];
#pragma unroll
    for (int c = 0; c < 32; c++) o[c] = 0.f;
#pragma unroll
    for (int j = 0; j < NJC; j++) {
        const __nv_bfloat16* pb = part + (slot0 + j) * (128 * 64) + (size_t)row * 64 + colh;
        const float wj = w[j];
#pragma unroll
        for (int c8 = 0; c8 < 4; c8++) {
            uint4 u = *(const uint4*)(pb + c8 * 8);
            float2 f0 = bf2_to_f2(u.x), f1 = bf2_to_f2(u.y);
            float2 f2 = bf2_to_f2(u.z), f3 = bf2_to_f2(u.w);
            o[c8 * 8 + 0] += wj * f0.x; o[c8 * 8 + 1] += wj * f0.y;
            o[c8 * 8 + 2] += wj * f1.x; o[c8 * 8 + 3] += wj * f1.y;
            o[c8 * 8 + 4] += wj * f2.x; o[c8 * 8 + 5] += wj * f2.y;
            o[c8 * 8 + 6] += wj * f3.x; o[c8 * 8 + 7] += wj * f3.y;
        }
    }

    __nv_bfloat16* ob = cxb + ((size_t)b * SS + iblk * 128 + row) * DVV + h * HEADV + colh;
#pragma unroll
    for (int c2 = 0; c2 < 16; c2++) {
        *(uint32_t*)(ob + c2 * 2) =
            pack2(__float2bfloat16(o[c2 * 2] * inv), __float2bfloat16(o[c2 * 2 + 1] * inv));
    }
}

// ======================= LayerNorm =========================================
__global__ __launch_bounds__(256)
void ln_kernel(const float* __restrict__ res, const float* __restrict__ gamma,
               const float* __restrict__ beta, float* __restrict__ out)
{
    const int row = blockIdx.x;
    const int c = threadIdx.x * 4;
    const float4 v = *(const float4*)(res + (size_t)row * DOUT + c);
    float s  = v.x + v.y + v.z + v.w;
    float s2 = v.x * v.x + v.y * v.y + v.z * v.z + v.w * v.w;
#pragma unroll
    for (int o = 16; o >= 1; o >>= 1) {
        s  += __shfl_xor_sync(0xffffffffu, s,  o);
        s2 += __shfl_xor_sync(0xffffffffu, s2, o);
    }
    __shared__ float sh[8], sh2[8];
    __shared__ float mu_s, inv_s;
    const int w = threadIdx.x >> 5;
    if ((threadIdx.x & 31) == 0) { sh[w] = s; sh2[w] = s2; }
    __syncthreads();
    if (threadIdx.x == 0) {
        float S = 0.f, S2 = 0.f;
#pragma unroll
        for (int i = 0; i < 8; i++) { S += sh[i]; S2 += sh2[i]; }
        const float mu = S * (1.f / DOUT);
        const float var = S2 * (1.f / DOUT) - mu * mu;
        mu_s = mu; inv_s = rsqrtf(var + LN_EPS);
    }
    __syncthreads();
    const float mu = mu_s, inv = inv_s;
    const float4 g  = *(const float4*)(gamma + c);
    const float4 bt = *(const float4*)(beta + c);
    float4 o;
    o.x = (v.x - mu) * inv * g.x + bt.x;
    o.y = (v.y - mu) * inv * g.y + bt.y;
    o.z = (v.z - mu) * inv * g.z + bt.z;
    o.w = (v.w - mu) * inv * g.w + bt.w;
    *(float4*)(out + (size_t)row * DOUT + c) = o;
}

// ===========================================================================
extern "C" void kernel_launch(void* const* d_in, const int* in_sizes, int n_in,
                              void* d_out, int out_size)
{
    const float* x      = (const float*)d_in[0];
    const float* Wq     = (const float*)d_in[1];
    const float* Wk     = (const float*)d_in[2];
    const float* Wcb    = (const float*)d_in[3];
    const float* Wv     = (const float*)d_in[4];
    const float* bv     = (const float*)d_in[5];
    const float* mixing = (const float*)d_in[6];
    const float* Wd     = (const float*)d_in[7];
    const float* bd     = (const float*)d_in[8];
    const float* gamma  = (const float*)d_in[9];
    const float* beta   = (const float*)d_in[10];
    float* out = (float*)d_out;

    float *res, *cbt, *pmv, *plv;
    __nv_bfloat16 *part, *qb, *kb, *vb, *xb, *wb, *vt, *cxb;
    cudaGetSymbolAddress((void**)&res,  g_res);
    cudaGetSymbolAddress((void**)&cbt,  g_cbt);
    cudaGetSymbolAddress((void**)&part, g_part);
    cudaGetSymbolAddress((void**)&pmv,  g_pm);
    cudaGetSymbolAddress((void**)&plv,  g_pl);
    cudaGetSymbolAddress((void**)&qb,   g_qb);
    cudaGetSymbolAddress((void**)&kb,   g_kb);
    cudaGetSymbolAddress((void**)&vb,   g_vb);
    cudaGetSymbolAddress((void**)&xb,   g_xb);
    cudaGetSymbolAddress((void**)&wb,   g_wb);
    cudaGetSymbolAddress((void**)&vt,   g_vt);
    cudaGetSymbolAddress((void**)&cxb,  g_cxb);

    cudaFuncSetAttribute(flash1_kernel,    cudaFuncAttributeMaxDynamicSharedMemorySize, FL_SMEM);
    cudaFuncSetAttribute(hmma1_nt_kernel,  cudaFuncAttributeMaxDynamicSharedMemorySize, 2 * P1_STAGE);
    cudaFuncSetAttribute(hmma1b_nt_kernel, cudaFuncAttributeMaxDynamicSharedMemorySize, 2 * P1_STAGE);

    const size_t WSZ = 1024 * 1024;

    // converts (fp32 -> bf16)
    cvt_bf_kernel<<<MROWS * DIN / 1024, 256>>>(x, xb);
    cvt_bf_kernel<<<WSZ / 1024, 256>>>(Wq, wb + 0 * WSZ);
    cvt_bf_kernel<<<WSZ / 1024, 256>>>(Wk, wb + 1 * WSZ);
    cvt_bf_kernel<<<WSZ / 1024, 256>>>(Wv, wb + 2 * WSZ);
    cvt_bf_kernel<<<WSZ / 1024, 256>>>(Wd, wb + 3 * WSZ);

    // projections (1-pass bf16 HMMA, bf16 outputs)
    dim3 gProj(DKK / 128, MROWS / 128);    // (8, 32)
    hmma1b_nt_kernel<<<gProj, 256, 2 * P1_STAGE>>>(xb, wb + 0 * WSZ, nullptr, qb, DKK);
    hmma1b_nt_kernel<<<gProj, 256, 2 * P1_STAGE>>>(xb, wb + 1 * WSZ, nullptr, kb, DKK);
    hmma1b_nt_kernel<<<gProj, 256, 2 * P1_STAGE>>>(xb, wb + 2 * WSZ, bv,      vb, DVV);
    cb_kernel<<<MROWS / 16, 256>>>(x, Wcb, cbt);

    // attention prep (V^T only; mixing folded into flash1)
    prep_vt_kernel<<<dim3(SS / 64, HEADV / 16, BH), 256>>>(vb, vt);

    // attention: split-K flash (phase 1) + combine (phase 2)
    flash1_kernel<<<dim3(NJC, SS / 128, BH), 256, FL_SMEM>>>(qb, kb, mixing, cbt, vt, part, pmv, plv);
    combine_kernel<<<dim3(SS / 128, BH), 256>>>(part, pmv, plv, cxb);

    // output projection + residual + LN
    hmma1_nt_kernel<<<gProj, 256, 2 * P1_STAGE>>>(cxb, wb + 3 * WSZ, bd, x, res, DOUT);
    ln_kernel<<<MROWS, 256>>>(res, gamma, beta, out);
}

// round 15
// speedup vs baseline: 1.0837x; 1.0837x over previous
#include <cuda_runtime.h>
#include <cuda_bf16.h>
#include <math.h>
#include <stdint.h>

// Problem constants
#define BB 2
#define SS 2048
#define DIN 1024
#define HH 16
#define DKK 1024
#define DVV 1024
#define DOUT 1024
#define MROWS (BB*SS)          // 4096
#define BH (BB*HH)             // 32
#define HEADV 64
#define SCALE 0.125f
#define LN_EPS 1e-5f
#define NJC 8                  // j-chunks of 256

// Scratch
__device__ float g_res[(size_t)MROWS * DOUT];
__device__ float g_cbt[(size_t)BH * SS];
__device__ __nv_bfloat16 g_part[(size_t)BH * 16 * NJC * 128 * 64];  // 64 MB
__device__ float g_pm[(size_t)BH * 16 * NJC * 128];
__device__ float g_pl[(size_t)BH * 16 * NJC * 128];
__device__ __nv_bfloat16 g_qm[(size_t)BH * SS * DKK];
__device__ __nv_bfloat16 g_qb[(size_t)MROWS * DKK];
__device__ __nv_bfloat16 g_kb[(size_t)MROWS * DKK];
__device__ __nv_bfloat16 g_vb[(size_t)MROWS * DVV];
__device__ __nv_bfloat16 g_xb[(size_t)MROWS * DIN];
__device__ __nv_bfloat16 g_wb[(size_t)4 * 1024 * 1024];
__device__ __nv_bfloat16 g_vt[(size_t)BH * HEADV * SS];
__device__ __nv_bfloat16 g_cxb[(size_t)MROWS * DVV];

// ======================= helpers ===========================================
__device__ __forceinline__ uint32_t smem_to_u32(const void* p) {
    uint32_t a;
    asm("{ .reg .u64 t; cvta.to.shared.u64 t, %1; cvt.u32.u64 %0, t; }" : "=r"(a) : "l"(p));
    return a;
}
__device__ __forceinline__ void cp16(uint32_t s, const void* g) {
    asm volatile("cp.async.cg.shared.global [%0], [%1], 16;" :: "r"(s), "l"(g));
}
#define CP_COMMIT() asm volatile("cp.async.commit_group;" ::: "memory")
#define CP_WAIT1()  asm volatile("cp.async.wait_group 1;" ::: "memory")
#define CP_WAIT0()  asm volatile("cp.async.wait_group 0;" ::: "memory")

__device__ __forceinline__ void ldsm_x4(uint32_t* r, uint32_t addr) {
    asm volatile("ldmatrix.sync.aligned.m8n8.x4.shared.b16 {%0,%1,%2,%3}, [%4];"
        : "=r"(r[0]), "=r"(r[1]), "=r"(r[2]), "=r"(r[3]) : "r"(addr));
}
__device__ __forceinline__ void ldsm_x2(uint32_t* r, uint32_t addr) {
    asm volatile("ldmatrix.sync.aligned.m8n8.x2.shared.b16 {%0,%1}, [%2];"
        : "=r"(r[0]), "=r"(r[1]) : "r"(addr));
}
__device__ __forceinline__ void mma_bf16(float* c, const uint32_t* a, const uint32_t* b) {
    asm volatile("mma.sync.aligned.m16n8k16.row.col.f32.bf16.bf16.f32 "
        "{%0,%1,%2,%3}, {%4,%5,%6,%7}, {%8,%9}, {%0,%1,%2,%3};"
        : "+f"(c[0]), "+f"(c[1]), "+f"(c[2]), "+f"(c[3])
        : "r"(a[0]), "r"(a[1]), "r"(a[2]), "r"(a[3]), "r"(b[0]), "r"(b[1]));
}
__device__ __forceinline__ uint32_t pack2(__nv_bfloat16 a, __nv_bfloat16 b) {
    return (uint32_t)__bfloat16_as_ushort(a) | ((uint32_t)__bfloat16_as_ushort(b) << 16);
}
__device__ __forceinline__ float2 bf2_to_f2(uint32_t u) {
    float2 r;
    r.x = __bfloat162float(__ushort_as_bfloat16((unsigned short)(u & 0xffffu)));
    r.y = __bfloat162float(__ushort_as_bfloat16((unsigned short)(u >> 16)));
    return r;
}

// ======================= fp32 -> bf16 convert ==============================
__global__ __launch_bounds__(256)
void cvt_bf_kernel(const float* __restrict__ in, __nv_bfloat16* __restrict__ o)
{
    const size_t i4 = (size_t)blockIdx.x * 256 + threadIdx.x;
    float4 v = *(const float4*)(in + i4 * 4);
    uint2 p;
    p.x = pack2(__float2bfloat16(v.x), __float2bfloat16(v.y));
    p.y = pack2(__float2bfloat16(v.z), __float2bfloat16(v.w));
    *(uint2*)(o + i4 * 4) = p;
}

// ======================= content bias (direct to cbt) ======================
__global__ __launch_bounds__(256)
void cb_kernel(const float* __restrict__ x, const float* __restrict__ Wcb,
               float* __restrict__ cbt)
{
    __shared__ float xs[16][132];
    const int tid = threadIdx.x;
    const int r = tid >> 4;
    const int h = tid & 15;
    const int row0 = blockIdx.x * 16;

    float acc = 0.f;
    for (int c0 = 0; c0 < DIN; c0 += 128) {
        __syncthreads();
#pragma unroll
        for (int i = 0; i < 2; i++) {
            const int id = tid + i * 256;
            const int rr = id >> 5, cc = (id & 31) * 4;
            *(float4*)&xs[rr][cc] = *(const float4*)(x + (size_t)(row0 + rr) * DIN + c0 + cc);
        }
        __syncthreads();
        const float4* wp = (const float4*)(Wcb + (size_t)h * DIN + c0);
#pragma unroll
        for (int i = 0; i < 32; i++) {
            float4 w = wp[i];
            float4 xv = *(const float4*)&xs[r][i * 4];
            acc += xv.x * w.x + xv.y * w.y + xv.z * w.z + xv.w * w.w;
        }
    }
    const int row = row0 + r;
    const int b = row >> 11, s = row & 2047;
    cbt[((size_t)(b * HH + h)) * SS + s] = acc * SCALE;
}

// ======================= 1-pass HMMA NT GEMM, fp32 out (out proj) ==========
#define P1_A 0
#define P1_B 16384
#define P1_STAGE 32768
#define P1_NST 16

__global__ __launch_bounds__(256)
void hmma1_nt_kernel(const __nv_bfloat16* __restrict__ Ap, const __nv_bfloat16* __restrict__ Bp,
                     const float* __restrict__ bias, const float* __restrict__ resid,
                     float* __restrict__ C, int N)
{
    extern __shared__ __align__(1024) char smem[];
    const uint32_t sb = smem_to_u32(smem);

    const int tid = threadIdx.x;
    const int wid = tid >> 5;
    const int lane = tid & 31;
    const int m0 = blockIdx.y * 128;
    const int n0 = blockIdx.x * 128;
    const int warp_m = wid >> 2;
    const int warp_n = wid & 3;

    const __nv_bfloat16* A_b = Ap + (size_t)m0 * DKK;
    const __nv_bfloat16* B_b = Bp + (size_t)n0 * DKK;

    float acc[4][4][4];
#pragma unroll
    for (int mt = 0; mt < 4; mt++)
#pragma unroll
        for (int nt = 0; nt < 4; nt++)
#pragma unroll
            for (int e = 0; e < 4; e++) acc[mt][nt][e] = 0.f;

    int cso[4];
    size_t cgi[4];
#pragma unroll
    for (int r = 0; r < 4; r++) {
        const int chunk = tid + 256 * r;
        const int row = chunk >> 3;
        const int cc = chunk & 7;
        cso[r] = row * 128 + ((cc * 16) ^ ((row & 7) << 4));
        cgi[r] = (size_t)row * DKK + cc * 8;
    }

    const int rowA = warp_m * 64 + (lane & 15);
    const int colA = ((lane >> 4) << 4);
    const uint32_t maskA = (rowA & 7) << 4;
    const int rowB = warp_n * 32 + (lane & 7);
    const int colB = ((lane >> 3) & 1) << 4;
    const uint32_t maskB = (rowB & 7) << 4;

    {
        const uint32_t st = sb;
#pragma unroll
        for (int r = 0; r < 4; r++) {
            cp16(st + P1_A + cso[r], A_b + cgi[r]);
            cp16(st + P1_B + cso[r], B_b + cgi[r]);
        }
        CP_COMMIT();
    }

    for (int s = 0; s < P1_NST; s++) {
        if (s + 1 < P1_NST) {
            const uint32_t st = sb + ((s + 1) & 1) * P1_STAGE;
            const size_t koff = (size_t)(s + 1) * 64;
#pragma unroll
            for (int r = 0; r < 4; r++) {
                cp16(st + P1_A + cso[r], A_b + cgi[r] + koff);
                cp16(st + P1_B + cso[r], B_b + cgi[r] + koff);
            }
            CP_COMMIT();
            CP_WAIT1();
        } else {
            CP_WAIT0();
        }
        __syncthreads();

        const uint32_t st = sb + (s & 1) * P1_STAGE;
#pragma unroll
        for (int ks = 0; ks < 4; ks++) {
            const int k0b = ks * 32;
            uint32_t Af[4][4], Bf[4][2];
#pragma unroll
            for (int mt = 0; mt < 4; mt++)
                ldsm_x4(Af[mt], st + P1_A + (uint32_t)((rowA + mt * 16) * 128) + (uint32_t)((k0b + colA) ^ maskA));
#pragma unroll
            for (int nt = 0; nt < 4; nt++)
                ldsm_x2(Bf[nt], st + P1_B + (uint32_t)((rowB + nt * 8) * 128) + (uint32_t)((k0b + colB) ^ maskB));
#pragma unroll
            for (int mt = 0; mt < 4; mt++)
#pragma unroll
                for (int nt = 0; nt < 4; nt++)
                    mma_bf16(acc[mt][nt], Af[mt], Bf[nt]);
        }
        __syncthreads();
    }

    const int r0 = lane >> 2;
    const int c0 = (lane & 3) * 2;
#pragma unroll
    for (int mt = 0; mt < 4; mt++) {
        const int mrow = m0 + warp_m * 64 + mt * 16 + r0;
#pragma unroll
        for (int nt = 0; nt < 4; nt++) {
            const int ncol = n0 + warp_n * 32 + nt * 8 + c0;
#pragma unroll
            for (int half = 0; half < 2; half++) {
                const int m = mrow + half * 8;
                float2 v = half ? make_float2(acc[mt][nt][2], acc[mt][nt][3])
                                : make_float2(acc[mt][nt][0], acc[mt][nt][1]);
                if (bias)  { v.x += bias[ncol]; v.y += bias[ncol + 1]; }
                if (resid) {
                    float2 rr = *(const float2*)(resid + (size_t)m * N + ncol);
                    v.x += rr.x; v.y += rr.y;
                }
                *(float2*)(C + (size_t)m * N + ncol) = v;
            }
        }
    }
}

// ======================= 1-pass HMMA NT GEMM, bf16 out (q/k/v proj) ========
__global__ __launch_bounds__(256)
void hmma1b_nt_kernel(const __nv_bfloat16* __restrict__ Ap, const __nv_bfloat16* __restrict__ Bp,
                      const float* __restrict__ bias, __nv_bfloat16* __restrict__ C, int N)
{
    extern __shared__ __align__(1024) char smem[];
    const uint32_t sb = smem_to_u32(smem);

    const int tid = threadIdx.x;
    const int wid = tid >> 5;
    const int lane = tid & 31;
    const int m0 = blockIdx.y * 128;
    const int n0 = blockIdx.x * 128;
    const int warp_m = wid >> 2;
    const int warp_n = wid & 3;

    const __nv_bfloat16* A_b = Ap + (size_t)m0 * DKK;
    const __nv_bfloat16* B_b = Bp + (size_t)n0 * DKK;

    float acc[4][4][4];
#pragma unroll
    for (int mt = 0; mt < 4; mt++)
#pragma unroll
        for (int nt = 0; nt < 4; nt++)
#pragma unroll
            for (int e = 0; e < 4; e++) acc[mt][nt][e] = 0.f;

    int cso[4];
    size_t cgi[4];
#pragma unroll
    for (int r = 0; r < 4; r++) {
        const int chunk = tid + 256 * r;
        const int row = chunk >> 3;
        const int cc = chunk & 7;
        cso[r] = row * 128 + ((cc * 16) ^ ((row & 7) << 4));
        cgi[r] = (size_t)row * DKK + cc * 8;
    }

    const int rowA = warp_m * 64 + (lane & 15);
    const int colA = ((lane >> 4) << 4);
    const uint32_t maskA = (rowA & 7) << 4;
    const int rowB = warp_n * 32 + (lane & 7);
    const int colB = ((lane >> 3) & 1) << 4;
    const uint32_t maskB = (rowB & 7) << 4;

    {
        const uint32_t st = sb;
#pragma unroll
        for (int r = 0; r < 4; r++) {
            cp16(st + P1_A + cso[r], A_b + cgi[r]);
            cp16(st + P1_B + cso[r], B_b + cgi[r]);
        }
        CP_COMMIT();
    }

    for (int s = 0; s < P1_NST; s++) {
        if (s + 1 < P1_NST) {
            const uint32_t st = sb + ((s + 1) & 1) * P1_STAGE;
            const size_t koff = (size_t)(s + 1) * 64;
#pragma unroll
            for (int r = 0; r < 4; r++) {
                cp16(st + P1_A + cso[r], A_b + cgi[r] + koff);
                cp16(st + P1_B + cso[r], B_b + cgi[r] + koff);
            }
            CP_COMMIT();
            CP_WAIT1();
        } else {
            CP_WAIT0();
        }
        __syncthreads();

        const uint32_t st = sb + (s & 1) * P1_STAGE;
#pragma unroll
        for (int ks = 0; ks < 4; ks++) {
            const int k0b = ks * 32;
            uint32_t Af[4][4], Bf[4][2];
#pragma unroll
            for (int mt = 0; mt < 4; mt++)
                ldsm_x4(Af[mt], st + P1_A + (uint32_t)((rowA + mt * 16) * 128) + (uint32_t)((k0b + colA) ^ maskA));
#pragma unroll
            for (int nt = 0; nt < 4; nt++)
                ldsm_x2(Bf[nt], st + P1_B + (uint32_t)((rowB + nt * 8) * 128) + (uint32_t)((k0b + colB) ^ maskB));
#pragma unroll
            for (int mt = 0; mt < 4; mt++)
#pragma unroll
                for (int nt = 0; nt < 4; nt++)
                    mma_bf16(acc[mt][nt], Af[mt], Bf[nt]);
        }
        __syncthreads();
    }

    const int r0 = lane >> 2;
    const int c0 = (lane & 3) * 2;
#pragma unroll
    for (int mt = 0; mt < 4; mt++) {
        const int mrow = m0 + warp_m * 64 + mt * 16 + r0;
#pragma unroll
        for (int nt = 0; nt < 4; nt++) {
            const int ncol = n0 + warp_n * 32 + nt * 8 + c0;
            float b0 = 0.f, b1 = 0.f;
            if (bias) { b0 = bias[ncol]; b1 = bias[ncol + 1]; }
#pragma unroll
            for (int half = 0; half < 2; half++) {
                const int m = mrow + half * 8;
                float vx = (half ? acc[mt][nt][2] : acc[mt][nt][0]) + b0;
                float vy = (half ? acc[mt][nt][3] : acc[mt][nt][1]) + b1;
                *(uint32_t*)(C + (size_t)m * N + ncol) =
                    pack2(__float2bfloat16(vx), __float2bfloat16(vy));
            }
        }
    }
}

// ======================= prep q (fold mixing*scale, bf16 in/out) ===========
__global__ __launch_bounds__(256)
void prep_q_kernel(const __nv_bfloat16* __restrict__ q, const float* __restrict__ mixing,
                   __nv_bfloat16* __restrict__ qm)
{
    const int bh = blockIdx.y;
    const int b = bh >> 4, h = bh & 15;
    const size_t i4 = (size_t)blockIdx.x * 256 + threadIdx.x;
    const int s = (int)(i4 >> 8);
    const int c4 = (int)(i4 & 255);
    uint2 qv = *(const uint2*)(q + ((size_t)b * SS + s) * DKK + c4 * 4);
    float2 q0 = bf2_to_f2(qv.x), q1 = bf2_to_f2(qv.y);
    float4 m = *(const float4*)(mixing + (size_t)h * DKK + c4 * 4);
    q0.x *= m.x * SCALE; q0.y *= m.y * SCALE;
    q1.x *= m.z * SCALE; q1.y *= m.w * SCALE;
    uint2 p;
    p.x = pack2(__float2bfloat16(q0.x), __float2bfloat16(q0.y));
    p.y = pack2(__float2bfloat16(q1.x), __float2bfloat16(q1.y));
    *(uint2*)(qm + ((size_t)bh * SS + s) * DKK + c4 * 4) = p;
}

// ======================= prep V^T per head (bf16 in) =======================
__global__ __launch_bounds__(256)
void prep_vt_kernel(const __nv_bfloat16* __restrict__ v, __nv_bfloat16* __restrict__ vt)
{
    const int tid = threadIdx.x;
    const int bh = blockIdx.z;
    const int b = bh >> 4, h = bh & 15;
    const int j = blockIdx.x * 64 + (tid & 63);
    const int vvg = blockIdx.y * 4 + (tid >> 6);
    uint2 v4 = *(const uint2*)(v + ((size_t)b * SS + j) * DVV + h * HEADV + vvg * 4);
    __nv_bfloat16 e0 = __ushort_as_bfloat16((unsigned short)(v4.x & 0xffffu));
    __nv_bfloat16 e1 = __ushort_as_bfloat16((unsigned short)(v4.x >> 16));
    __nv_bfloat16 e2 = __ushort_as_bfloat16((unsigned short)(v4.y & 0xffffu));
    __nv_bfloat16 e3 = __ushort_as_bfloat16((unsigned short)(v4.y >> 16));
    const size_t ob = ((size_t)bh * HEADV + vvg * 4) * SS + j;
    vt[ob + 0 * SS] = e0;
    vt[ob + 1 * SS] = e1;
    vt[ob + 2 * SS] = e2;
    vt[ob + 3 * SS] = e3;
}

// ======================= phase 1: QK + local softmax + PV ==================
#define SC_A  0
#define SC_B  16384
#define SC_STAGE 49152
#define SC_NST 16
#define FL_P   0
#define FL_V   65536
#define FL_STAT 98304
#define FL_M    100352
#define FL_L    100864
#define FL_SMEM 101376

__global__ __launch_bounds__(256, 1)
void flash1_kernel(const __nv_bfloat16* __restrict__ qm, const __nv_bfloat16* __restrict__ kb,
                   const float* __restrict__ cbt, const __nv_bfloat16* __restrict__ vt,
                   __nv_bfloat16* __restrict__ part, float* __restrict__ pm, float* __restrict__ pl)
{
    extern __shared__ __align__(1024) char smem[];
    const uint32_t sb = smem_to_u32(smem);
    float* sm_stat = (float*)(smem + FL_STAT);
    float* sm_m    = (float*)(smem + FL_M);
    float* sm_l    = (float*)(smem + FL_L);

    const int tid = threadIdx.x;
    const int wid = tid >> 5;
    const int lane = tid & 31;
    const int jc = blockIdx.x;
    const int iblk = blockIdx.y;
    const int bh = blockIdx.z;
    const int b = bh >> 4;
    const int i0 = iblk * 128;
    const int j0 = jc * 256;
    const int warp_m = wid >> 2;
    const int warp_n = wid & 3;

    const __nv_bfloat16* qm_b = qm + ((size_t)bh * SS + i0) * DKK;
    const __nv_bfloat16* kb_b = kb + ((size_t)b * SS + j0) * DKK;

    float acc[4][8][4];
#pragma unroll
    for (int mt = 0; mt < 4; mt++)
#pragma unroll
        for (int nn = 0; nn < 8; nn++)
#pragma unroll
            for (int e = 0; e < 4; e++) acc[mt][nn][e] = 0.f;

    int csoA[4];  size_t cgiA[4];
#pragma unroll
    for (int r = 0; r < 4; r++) {
        const int chunk = tid + 256 * r;
        const int row = chunk >> 3, cc = chunk & 7;
        csoA[r] = row * 128 + ((cc * 16) ^ ((row & 7) << 4));
        cgiA[r] = (size_t)row * DKK + cc * 8;
    }
    int csoB[8];  size_t cgiB[8];
#pragma unroll
    for (int r = 0; r < 8; r++) {
        const int chunk = tid + 256 * r;
        const int row = chunk >> 3, cc = chunk & 7;
        csoB[r] = row * 128 + ((cc * 16) ^ ((row & 7) << 4));
        cgiB[r] = (size_t)row * DKK + cc * 8;
    }

    // ---- QK^T mainloop (R13 exact) ---------------------------------------
    {
        const uint32_t st = sb;
#pragma unroll
        for (int r = 0; r < 4; r++)
            cp16(st + SC_A + csoA[r], qm_b + cgiA[r]);
#pragma unroll
        for (int r = 0; r < 8; r++)
            cp16(st + SC_B + csoB[r], kb_b + cgiB[r]);
        CP_COMMIT();
    }

    for (int s = 0; s < SC_NST; s++) {
        if (s + 1 < SC_NST) {
            const uint32_t st = sb + ((s + 1) & 1) * SC_STAGE;
            const size_t koff = (size_t)(s + 1) * 64;
#pragma unroll
            for (int r = 0; r < 4; r++)
                cp16(st + SC_A + csoA[r], qm_b + cgiA[r] + koff);
#pragma unroll
            for (int r = 0; r < 8; r++)
                cp16(st + SC_B + csoB[r], kb_b + cgiB[r] + koff);
            CP_COMMIT();
            CP_WAIT1();
        } else {
            CP_WAIT0();
        }
        __syncthreads();

        const uint32_t st = sb + (s & 1) * SC_STAGE;
#pragma unroll
        for (int ks = 0; ks < 4; ks++) {
            const int k0b = ks * 32;
            uint32_t Af[4][4];
#pragma unroll
            for (int mt = 0; mt < 4; mt++) {
                const int rowA = warp_m * 64 + mt * 16 + (lane & 15);
                const uint32_t cA = (uint32_t)((k0b + ((lane >> 4) << 4)) ^ ((rowA & 7) << 4));
                ldsm_x4(Af[mt], st + SC_A + (uint32_t)(rowA * 128) + cA);
            }
#pragma unroll
            for (int ng = 0; ng < 4; ng++) {
                const int rowB = warp_n * 64 + ng * 16 + (lane & 7) + ((lane & 16) >> 1);
                const uint32_t cB = (uint32_t)((k0b + (((lane >> 3) & 1) << 4)) ^ ((rowB & 7) << 4));
                uint32_t B4[4];
                ldsm_x4(B4, st + SC_B + (uint32_t)(rowB * 128) + cB);
#pragma unroll
                for (int mt = 0; mt < 4; mt++) {
                    mma_bf16(acc[mt][ng * 2 + 0], Af[mt], B4 + 0);
                    mma_bf16(acc[mt][ng * 2 + 1], Af[mt], B4 + 2);
                }
            }
        }
        __syncthreads();
    }

    // ---- V prefetch into freed stage smem --------------------------------
#pragma unroll
    for (int c = 0; c < 2; c++) {
#pragma unroll
        for (int r = 0; r < 4; r++) {
            const int id = tid + 256 * r;
            const int row = id >> 4, cc = id & 15;
            const uint32_t so = (uint32_t)(row * 256 + ((cc * 16) ^ ((row & 7) << 4)));
            const size_t gi = ((size_t)bh * HEADV + row) * SS + j0 + c * 128 + cc * 8;
            cp16(sb + FL_V + c * 16384 + so, vt + gi);
        }
    }
    CP_COMMIT();

    // ---- add content bias, row max ---------------------------------------
    const float* cbp = cbt + (size_t)bh * SS + j0;
    float rmax[8];
#pragma unroll
    for (int i = 0; i < 8; i++) rmax[i] = -INFINITY;
#pragma unroll
    for (int nn = 0; nn < 8; nn++) {
        float2 cb2 = *(const float2*)(cbp + warp_n * 64 + nn * 8 + (lane & 3) * 2);
#pragma unroll
        for (int mt = 0; mt < 4; mt++) {
            acc[mt][nn][0] += cb2.x; acc[mt][nn][1] += cb2.y;
            acc[mt][nn][2] += cb2.x; acc[mt][nn][3] += cb2.y;
            rmax[mt * 2 + 0] = fmaxf(rmax[mt * 2 + 0], fmaxf(acc[mt][nn][0], acc[mt][nn][1]));
            rmax[mt * 2 + 1] = fmaxf(rmax[mt * 2 + 1], fmaxf(acc[mt][nn][2], acc[mt][nn][3]));
        }
    }
#pragma unroll
    for (int i = 0; i < 8; i++) {
        rmax[i] = fmaxf(rmax[i], __shfl_xor_sync(0xffffffffu, rmax[i], 1));
        rmax[i] = fmaxf(rmax[i], __shfl_xor_sync(0xffffffffu, rmax[i], 2));
    }
    if ((lane & 3) == 0) {
#pragma unroll
        for (int mt = 0; mt < 4; mt++) {
            const int r = warp_m * 64 + mt * 16 + (lane >> 2);
            sm_stat[(r + 0) * 4 + warp_n] = rmax[mt * 2 + 0];
            sm_stat[(r + 8) * 4 + warp_n] = rmax[mt * 2 + 1];
        }
    }
    __syncthreads();
    if (tid < 128) {
        sm_m[tid] = fmaxf(fmaxf(sm_stat[tid * 4 + 0], sm_stat[tid * 4 + 1]),
                          fmaxf(sm_stat[tid * 4 + 2], sm_stat[tid * 4 + 3]));
    }
    __syncthreads();

    // ---- exp, P store (512B pitch), partial sums -------------------------
    float rsum[8];
#pragma unroll
    for (int i = 0; i < 8; i++) rsum[i] = 0.f;
#pragma unroll
    for (int mt = 0; mt < 4; mt++) {
        const int r0 = warp_m * 64 + mt * 16 + (lane >> 2);
        const float mn0 = sm_m[r0];
        const float mn1 = sm_m[r0 + 8];
        const uint32_t off0base = (uint32_t)(r0 * 512);
        const uint32_t off1base = (uint32_t)((r0 + 8) * 512);
        const uint32_t mask0 = (uint32_t)((r0 & 7) << 4);
        const uint32_t mask1 = (uint32_t)(((r0 + 8) & 7) << 4);
#pragma unroll
        for (int nn = 0; nn < 8; nn++) {
            float p0 = __expf(acc[mt][nn][0] - mn0);
            float p1 = __expf(acc[mt][nn][1] - mn0);
            float p2 = __expf(acc[mt][nn][2] - mn1);
            float p3 = __expf(acc[mt][nn][3] - mn1);
            rsum[mt * 2 + 0] += p0 + p1;
            rsum[mt * 2 + 1] += p2 + p3;
            const uint32_t colbyte = (uint32_t)((warp_n * 64 + nn * 8 + (lane & 3) * 2) * 2);
            *(uint32_t*)(smem + FL_P + off0base + (colbyte ^ mask0)) = pack2(__float2bfloat16(p0), __float2bfloat16(p1));
            *(uint32_t*)(smem + FL_P + off1base + (colbyte ^ mask1)) = pack2(__float2bfloat16(p2), __float2bfloat16(p3));
        }
    }
#pragma unroll
    for (int i = 0; i < 8; i++) {
        rsum[i] += __shfl_xor_sync(0xffffffffu, rsum[i], 1);
        rsum[i] += __shfl_xor_sync(0xffffffffu, rsum[i], 2);
    }
    if ((lane & 3) == 0) {
#pragma unroll
        for (int mt = 0; mt < 4; mt++) {
            const int r = warp_m * 64 + mt * 16 + (lane >> 2);
            sm_stat[(r + 0) * 4 + warp_n] = rsum[mt * 2 + 0];
            sm_stat[(r + 8) * 4 + warp_n] = rsum[mt * 2 + 1];
        }
    }
    __syncthreads();
    if (tid < 128) {
        sm_l[tid] = sm_stat[tid * 4 + 0] + sm_stat[tid * 4 + 1]
                  + sm_stat[tid * 4 + 2] + sm_stat[tid * 4 + 3];
    }
    CP_WAIT0();
    __syncthreads();

    // ---- PV: O = P(128x256) @ V^T ----------------------------------------
    float O[8][4];
#pragma unroll
    for (int nn = 0; nn < 8; nn++)
#pragma unroll
        for (int e = 0; e < 4; e++) O[nn][e] = 0.f;

    const int m0w = wid * 16;
#pragma unroll
    for (int ks = 0; ks < 16; ks++) {
        const int chunk = ks >> 3;
        const int k0b = (ks & 7) * 32;
        uint32_t P4[4];
        const int rowa = m0w + (lane & 15);
        const uint32_t cA = (uint32_t)((ks * 32 + ((lane >> 4) << 4)) ^ ((rowa & 7) << 4));
        ldsm_x4(P4, sb + FL_P + (uint32_t)(rowa * 512) + cA);
        const uint32_t vbase = sb + FL_V + chunk * 16384;
#pragma unroll
        for (int ng = 0; ng < 4; ng++) {
            const int rowb = ng * 16 + (lane & 7) + ((lane & 16) >> 1);
            const uint32_t cB = (uint32_t)((k0b + (((lane >> 3) & 1) << 4)) ^ ((rowb & 7) << 4));
            uint32_t V4[4];
            ldsm_x4(V4, vbase + (uint32_t)(rowb * 256) + cB);
            mma_bf16(O[ng * 2 + 0], P4, V4 + 0);
            mma_bf16(O[ng * 2 + 1], P4, V4 + 2);
        }
    }

    // ---- write partial O (bf16) + stats ----------------------------------
    const size_t slot = ((size_t)bh * 16 + iblk) * NJC + jc;
    __nv_bfloat16* pbase = part + slot * (128 * 64);
    const int r0 = m0w + (lane >> 2);
    const int r1 = r0 + 8;
    const int c0 = (lane & 3) * 2;
#pragma unroll
    for (int nn = 0; nn < 8; nn++) {
        const int col = nn * 8 + c0;
        *(uint32_t*)(pbase + (size_t)r0 * 64 + col) = pack2(__float2bfloat16(O[nn][0]), __float2bfloat16(O[nn][1]));
        *(uint32_t*)(pbase + (size_t)r1 * 64 + col) = pack2(__float2bfloat16(O[nn][2]), __float2bfloat16(O[nn][3]));
    }
    if (tid < 128) {
        pm[slot * 128 + tid] = sm_m[tid];
        pl[slot * 128 + tid] = sm_l[tid];
    }
}

// ======================= phase 2: combine partials =========================
__global__ __launch_bounds__(256)
void combine_kernel(const __nv_bfloat16* __restrict__ part, const float* __restrict__ pm,
                    const float* __restrict__ pl, __nv_bfloat16* __restrict__ cxb)
{
    const int tid = threadIdx.x;
    const int iblk = blockIdx.x;
    const int bh = blockIdx.y;
    const int b = bh >> 4, h = bh & 15;
    const int row = tid >> 1;
    const int colh = (tid & 1) * 32;

    const size_t slot0 = ((size_t)bh * 16 + iblk) * NJC;

    float mj[NJC], w[NJC];
    float m = -INFINITY;
#pragma unroll
    for (int j = 0; j < NJC; j++) {
        mj[j] = pm[(slot0 + j) * 128 + row];
        m = fmaxf(m, mj[j]);
    }
    float lsum = 0.f;
#pragma unroll
    for (int j = 0; j < NJC; j++) {
        w[j] = __expf(mj[j] - m);
        lsum += pl[(slot0 + j) * 128 + row] * w[j];
    }
    const float inv = 1.f / lsum;

    float o[32];
#pragma unroll
    for (int c = 0; c < 32; c++) o[c] = 0.f;
#pragma unroll
    for (int j = 0; j < NJC; j++) {
        const __nv_bfloat16* pb = part + (slot0 + j) * (128 * 64) + (size_t)row * 64 + colh;
        const float wj = w[j];
#pragma unroll
        for (int c8 = 0; c8 < 4; c8++) {
            uint4 u = *(const uint4*)(pb + c8 * 8);
            float2 f0 = bf2_to_f2(u.x), f1 = bf2_to_f2(u.y);
            float2 f2 = bf2_to_f2(u.z), f3 = bf2_to_f2(u.w);
            o[c8 * 8 + 0] += wj * f0.x; o[c8 * 8 + 1] += wj * f0.y;
            o[c8 * 8 + 2] += wj * f1.x; o[c8 * 8 + 3] += wj * f1.y;
            o[c8 * 8 + 4] += wj * f2.x; o[c8 * 8 + 5] += wj * f2.y;
            o[c8 * 8 + 6] += wj * f3.x; o[c8 * 8 + 7] += wj * f3.y;
        }
    }

    __nv_bfloat16* ob = cxb + ((size_t)b * SS + iblk * 128 + row) * DVV + h * HEADV + colh;
#pragma unroll
    for (int c2 = 0; c2 < 16; c2++) {
        *(uint32_t*)(ob + c2 * 2) =
            pack2(__float2bfloat16(o[c2 * 2] * inv), __float2bfloat16(o[c2 * 2 + 1] * inv));
    }
}

// ======================= LayerNorm =========================================
__global__ __launch_bounds__(256)
void ln_kernel(const float* __restrict__ res, const float* __restrict__ gamma,
               const float* __restrict__ beta, float* __restrict__ out)
{
    const int row = blockIdx.x;
    const int c = threadIdx.x * 4;
    const float4 v = *(const float4*)(res + (size_t)row * DOUT + c);
    float s  = v.x + v.y + v.z + v.w;
    float s2 = v.x * v.x + v.y * v.y + v.z * v.z + v.w * v.w;
#pragma unroll
    for (int o = 16; o >= 1; o >>= 1) {
        s  += __shfl_xor_sync(0xffffffffu, s,  o);
        s2 += __shfl_xor_sync(0xffffffffu, s2, o);
    }
    __shared__ float sh[8], sh2[8];
    __shared__ float mu_s, inv_s;
    const int w = threadIdx.x >> 5;
    if ((threadIdx.x & 31) == 0) { sh[w] = s; sh2[w] = s2; }
    __syncthreads();
    if (threadIdx.x == 0) {
        float S = 0.f, S2 = 0.f;
#pragma unroll
        for (int i = 0; i < 8; i++) { S += sh[i]; S2 += sh2[i]; }
        const float mu = S * (1.f / DOUT);
        const float var = S2 * (1.f / DOUT) - mu * mu;
        mu_s = mu; inv_s = rsqrtf(var + LN_EPS);
    }
    __syncthreads();
    const float mu = mu_s, inv = inv_s;
    const float4 g  = *(const float4*)(gamma + c);
    const float4 bt = *(const float4*)(beta + c);
    float4 o;
    o.x = (v.x - mu) * inv * g.x + bt.x;
    o.y = (v.y - mu) * inv * g.y + bt.y;
    o.z = (v.z - mu) * inv * g.z + bt.z;
    o.w = (v.w - mu) * inv * g.w + bt.w;
    *(float4*)(out + (size_t)row * DOUT + c) = o;
}

// ===========================================================================
extern "C" void kernel_launch(void* const* d_in, const int* in_sizes, int n_in,
                              void* d_out, int out_size)
{
    const float* x      = (const float*)d_in[0];
    const float* Wq     = (const float*)d_in[1];
    const float* Wk     = (const float*)d_in[2];
    const float* Wcb    = (const float*)d_in[3];
    const float* Wv     = (const float*)d_in[4];
    const float* bv     = (const float*)d_in[5];
    const float* mixing = (const float*)d_in[6];
    const float* Wd     = (const float*)d_in[7];
    const float* bd     = (const float*)d_in[8];
    const float* gamma  = (const float*)d_in[9];
    const float* beta   = (const float*)d_in[10];
    float* out = (float*)d_out;

    float *res, *cbt, *pmv, *plv;
    __nv_bfloat16 *part, *qm, *qb, *kb, *vb, *xb, *wb, *vt, *cxb;
    cudaGetSymbolAddress((void**)&res,  g_res);
    cudaGetSymbolAddress((void**)&cbt,  g_cbt);
    cudaGetSymbolAddress((void**)&part, g_part);
    cudaGetSymbolAddress((void**)&pmv,  g_pm);
    cudaGetSymbolAddress((void**)&plv,  g_pl);
    cudaGetSymbolAddress((void**)&qm,   g_qm);
    cudaGetSymbolAddress((void**)&qb,   g_qb);
    cudaGetSymbolAddress((void**)&kb,   g_kb);
    cudaGetSymbolAddress((void**)&vb,   g_vb);
    cudaGetSymbolAddress((void**)&xb,   g_xb);
    cudaGetSymbolAddress((void**)&wb,   g_wb);
    cudaGetSymbolAddress((void**)&vt,   g_vt);
    cudaGetSymbolAddress((void**)&cxb,  g_cxb);

    cudaFuncSetAttribute(flash1_kernel,    cudaFuncAttributeMaxDynamicSharedMemorySize, FL_SMEM);
    cudaFuncSetAttribute(hmma1_nt_kernel,  cudaFuncAttributeMaxDynamicSharedMemorySize, 2 * P1_STAGE);
    cudaFuncSetAttribute(hmma1b_nt_kernel, cudaFuncAttributeMaxDynamicSharedMemorySize, 2 * P1_STAGE);

    const size_t WSZ = 1024 * 1024;

    // converts (fp32 -> bf16)
    cvt_bf_kernel<<<MROWS * DIN / 1024, 256>>>(x, xb);
    cvt_bf_kernel<<<WSZ / 1024, 256>>>(Wq, wb + 0 * WSZ);
    cvt_bf_kernel<<<WSZ / 1024, 256>>>(Wk, wb + 1 * WSZ);
    cvt_bf_kernel<<<WSZ / 1024, 256>>>(Wv, wb + 2 * WSZ);
    cvt_bf_kernel<<<WSZ / 1024, 256>>>(Wd, wb + 3 * WSZ);

    // projections (1-pass bf16 HMMA, bf16 outputs)
    dim3 gProj(DKK / 128, MROWS / 128);    // (8, 32)
    hmma1b_nt_kernel<<<gProj, 256, 2 * P1_STAGE>>>(xb, wb + 0 * WSZ, nullptr, qb, DKK);
    hmma1b_nt_kernel<<<gProj, 256, 2 * P1_STAGE>>>(xb, wb + 1 * WSZ, nullptr, kb, DKK);
    hmma1b_nt_kernel<<<gProj, 256, 2 * P1_STAGE>>>(xb, wb + 2 * WSZ, bv,      vb, DVV);
    cb_kernel<<<MROWS / 16, 256>>>(x, Wcb, cbt);

    // attention preps
    prep_q_kernel<<<dim3(SS * DKK / 4 / 256, BH), 256>>>(qb, mixing, qm);
    prep_vt_kernel<<<dim3(SS / 64, HEADV / 16, BH), 256>>>(vb, vt);

    // attention: split-K flash (phase 1) + combine (phase 2)
    flash1_kernel<<<dim3(NJC, SS / 128, BH), 256, FL_SMEM>>>(qm, kb, cbt, vt, part, pmv, plv);
    combine_kernel<<<dim3(SS / 128, BH), 256>>>(part, pmv, plv, cxb);

    // output projection + residual + LN
    hmma1_nt_kernel<<<gProj, 256, 2 * P1_STAGE>>>(cxb, wb + 3 * WSZ, bd, x, res, DOUT);
    ln_kernel<<<MROWS, 256>>>(res, gamma, beta, out);
}

// round 16
// speedup vs baseline: 1.0907x; 1.0065x over previous
#include <cuda_runtime.h>
#include <cuda_bf16.h>
#include <math.h>
#include <stdint.h>

// Problem constants
#define BB 2
#define SS 2048
#define DIN 1024
#define HH 16
#define DKK 1024
#define DVV 1024
#define DOUT 1024
#define MROWS (BB*SS)          // 4096
#define BH (BB*HH)             // 32
#define HEADV 64
#define SCALE 0.125f
#define LN_EPS 1e-5f
#define NJC 8                  // j-chunks of 256

// Scratch
__device__ float g_res[(size_t)MROWS * DOUT];
__device__ float g_cbt[(size_t)BH * SS];
__device__ __nv_bfloat16 g_part[(size_t)BH * 16 * NJC * 128 * 64];  // 64 MB
__device__ float g_pm[(size_t)BH * 16 * NJC * 128];
__device__ float g_pl[(size_t)BH * 16 * NJC * 128];
__device__ __nv_bfloat16 g_qm[(size_t)BH * SS * DKK];
__device__ __nv_bfloat16 g_qb[(size_t)MROWS * DKK];
__device__ __nv_bfloat16 g_kb[(size_t)MROWS * DKK];
__device__ __nv_bfloat16 g_vb[(size_t)MROWS * DVV];
__device__ __nv_bfloat16 g_xb[(size_t)MROWS * DIN];
__device__ __nv_bfloat16 g_wb[(size_t)4 * 1024 * 1024];
__device__ __nv_bfloat16 g_vt[(size_t)BH * HEADV * SS];
__device__ __nv_bfloat16 g_cxb[(size_t)MROWS * DVV];

// ======================= helpers ===========================================
__device__ __forceinline__ uint32_t smem_to_u32(const void* p) {
    uint32_t a;
    asm("{ .reg .u64 t; cvta.to.shared.u64 t, %1; cvt.u32.u64 %0, t; }" : "=r"(a) : "l"(p));
    return a;
}
__device__ __forceinline__ void cp16(uint32_t s, const void* g) {
    asm volatile("cp.async.cg.shared.global [%0], [%1], 16;" :: "r"(s), "l"(g));
}
#define CP_COMMIT() asm volatile("cp.async.commit_group;" ::: "memory")
#define CP_WAIT1()  asm volatile("cp.async.wait_group 1;" ::: "memory")
#define CP_WAIT0()  asm volatile("cp.async.wait_group 0;" ::: "memory")

__device__ __forceinline__ void ldsm_x4(uint32_t* r, uint32_t addr) {
    asm volatile("ldmatrix.sync.aligned.m8n8.x4.shared.b16 {%0,%1,%2,%3}, [%4];"
        : "=r"(r[0]), "=r"(r[1]), "=r"(r[2]), "=r"(r[3]) : "r"(addr));
}
__device__ __forceinline__ void ldsm_x2(uint32_t* r, uint32_t addr) {
    asm volatile("ldmatrix.sync.aligned.m8n8.x2.shared.b16 {%0,%1}, [%2];"
        : "=r"(r[0]), "=r"(r[1]) : "r"(addr));
}
__device__ __forceinline__ void mma_bf16(float* c, const uint32_t* a, const uint32_t* b) {
    asm volatile("mma.sync.aligned.m16n8k16.row.col.f32.bf16.bf16.f32 "
        "{%0,%1,%2,%3}, {%4,%5,%6,%7}, {%8,%9}, {%0,%1,%2,%3};"
        : "+f"(c[0]), "+f"(c[1]), "+f"(c[2]), "+f"(c[3])
        : "r"(a[0]), "r"(a[1]), "r"(a[2]), "r"(a[3]), "r"(b[0]), "r"(b[1]));
}
__device__ __forceinline__ uint32_t pack2(__nv_bfloat16 a, __nv_bfloat16 b) {
    return (uint32_t)__bfloat16_as_ushort(a) | ((uint32_t)__bfloat16_as_ushort(b) << 16);
}
__device__ __forceinline__ float2 bf2_to_f2(uint32_t u) {
    float2 r;
    r.x = __bfloat162float(__ushort_as_bfloat16((unsigned short)(u & 0xffffu)));
    r.y = __bfloat162float(__ushort_as_bfloat16((unsigned short)(u >> 16)));
    return r;
}

// ======================= fp32 -> bf16 converts =============================
__global__ __launch_bounds__(256)
void cvt_bf_kernel(const float* __restrict__ in, __nv_bfloat16* __restrict__ o)
{
    const size_t i4 = (size_t)blockIdx.x * 256 + threadIdx.x;
    float4 v = *(const float4*)(in + i4 * 4);
    uint2 p;
    p.x = pack2(__float2bfloat16(v.x), __float2bfloat16(v.y));
    p.y = pack2(__float2bfloat16(v.z), __float2bfloat16(v.w));
    *(uint2*)(o + i4 * 4) = p;
}

// 4 weights in one launch: blockIdx.y selects source; dst = wb + y*1M
__global__ __launch_bounds__(256)
void cvt_w4_kernel(const float* __restrict__ w0, const float* __restrict__ w1,
                   const float* __restrict__ w2, const float* __restrict__ w3,
                   __nv_bfloat16* __restrict__ wb)
{
    const float* src = (blockIdx.y == 0) ? w0 : (blockIdx.y == 1) ? w1
                     : (blockIdx.y == 2) ? w2 : w3;
    const size_t i4 = (size_t)blockIdx.x * 256 + threadIdx.x;
    float4 v = *(const float4*)(src + i4 * 4);
    uint2 p;
    p.x = pack2(__float2bfloat16(v.x), __float2bfloat16(v.y));
    p.y = pack2(__float2bfloat16(v.z), __float2bfloat16(v.w));
    *(uint2*)(wb + (size_t)blockIdx.y * 1024 * 1024 + i4 * 4) = p;
}

// ======================= content bias (direct to cbt) ======================
__global__ __launch_bounds__(256)
void cb_kernel(const float* __restrict__ x, const float* __restrict__ Wcb,
               float* __restrict__ cbt)
{
    __shared__ float xs[16][132];
    const int tid = threadIdx.x;
    const int r = tid >> 4;
    const int h = tid & 15;
    const int row0 = blockIdx.x * 16;

    float acc = 0.f;
    for (int c0 = 0; c0 < DIN; c0 += 128) {
        __syncthreads();
#pragma unroll
        for (int i = 0; i < 2; i++) {
            const int id = tid + i * 256;
            const int rr = id >> 5, cc = (id & 31) * 4;
            *(float4*)&xs[rr][cc] = *(const float4*)(x + (size_t)(row0 + rr) * DIN + c0 + cc);
        }
        __syncthreads();
        const float4* wp = (const float4*)(Wcb + (size_t)h * DIN + c0);
#pragma unroll
        for (int i = 0; i < 32; i++) {
            float4 w = wp[i];
            float4 xv = *(const float4*)&xs[r][i * 4];
            acc += xv.x * w.x + xv.y * w.y + xv.z * w.z + xv.w * w.w;
        }
    }
    const int row = row0 + r;
    const int b = row >> 11, s = row & 2047;
    cbt[((size_t)(b * HH + h)) * SS + s] = acc * SCALE;
}

// ======================= 1-pass HMMA NT GEMM, fp32 out (out proj) ==========
#define P1_A 0
#define P1_B 16384
#define P1_STAGE 32768
#define P1_NST 16

__global__ __launch_bounds__(256)
void hmma1_nt_kernel(const __nv_bfloat16* __restrict__ Ap, const __nv_bfloat16* __restrict__ Bp,
                     const float* __restrict__ bias, const float* __restrict__ resid,
                     float* __restrict__ C, int N)
{
    extern __shared__ __align__(1024) char smem[];
    const uint32_t sb = smem_to_u32(smem);

    const int tid = threadIdx.x;
    const int wid = tid >> 5;
    const int lane = tid & 31;
    const int m0 = blockIdx.y * 128;
    const int n0 = blockIdx.x * 128;
    const int warp_m = wid >> 2;
    const int warp_n = wid & 3;

    const __nv_bfloat16* A_b = Ap + (size_t)m0 * DKK;
    const __nv_bfloat16* B_b = Bp + (size_t)n0 * DKK;

    float acc[4][4][4];
#pragma unroll
    for (int mt = 0; mt < 4; mt++)
#pragma unroll
        for (int nt = 0; nt < 4; nt++)
#pragma unroll
            for (int e = 0; e < 4; e++) acc[mt][nt][e] = 0.f;

    int cso[4];
    size_t cgi[4];
#pragma unroll
    for (int r = 0; r < 4; r++) {
        const int chunk = tid + 256 * r;
        const int row = chunk >> 3;
        const int cc = chunk & 7;
        cso[r] = row * 128 + ((cc * 16) ^ ((row & 7) << 4));
        cgi[r] = (size_t)row * DKK + cc * 8;
    }

    const int rowA = warp_m * 64 + (lane & 15);
    const int colA = ((lane >> 4) << 4);
    const uint32_t maskA = (rowA & 7) << 4;
    const int rowB = warp_n * 32 + (lane & 7);
    const int colB = ((lane >> 3) & 1) << 4;
    const uint32_t maskB = (rowB & 7) << 4;

    {
        const uint32_t st = sb;
#pragma unroll
        for (int r = 0; r < 4; r++) {
            cp16(st + P1_A + cso[r], A_b + cgi[r]);
            cp16(st + P1_B + cso[r], B_b + cgi[r]);
        }
        CP_COMMIT();
    }

    for (int s = 0; s < P1_NST; s++) {
        if (s + 1 < P1_NST) {
            const uint32_t st = sb + ((s + 1) & 1) * P1_STAGE;
            const size_t koff = (size_t)(s + 1) * 64;
#pragma unroll
            for (int r = 0; r < 4; r++) {
                cp16(st + P1_A + cso[r], A_b + cgi[r] + koff);
                cp16(st + P1_B + cso[r], B_b + cgi[r] + koff);
            }
            CP_COMMIT();
            CP_WAIT1();
        } else {
            CP_WAIT0();
        }
        __syncthreads();

        const uint32_t st = sb + (s & 1) * P1_STAGE;
#pragma unroll
        for (int ks = 0; ks < 4; ks++) {
            const int k0b = ks * 32;
            uint32_t Af[4][4], Bf[4][2];
#pragma unroll
            for (int mt = 0; mt < 4; mt++)
                ldsm_x4(Af[mt], st + P1_A + (uint32_t)((rowA + mt * 16) * 128) + (uint32_t)((k0b + colA) ^ maskA));
#pragma unroll
            for (int nt = 0; nt < 4; nt++)
                ldsm_x2(Bf[nt], st + P1_B + (uint32_t)((rowB + nt * 8) * 128) + (uint32_t)((k0b + colB) ^ maskB));
#pragma unroll
            for (int mt = 0; mt < 4; mt++)
#pragma unroll
                for (int nt = 0; nt < 4; nt++)
                    mma_bf16(acc[mt][nt], Af[mt], Bf[nt]);
        }
        __syncthreads();
    }

    const int r0 = lane >> 2;
    const int c0 = (lane & 3) * 2;
#pragma unroll
    for (int mt = 0; mt < 4; mt++) {
        const int mrow = m0 + warp_m * 64 + mt * 16 + r0;
#pragma unroll
        for (int nt = 0; nt < 4; nt++) {
            const int ncol = n0 + warp_n * 32 + nt * 8 + c0;
#pragma unroll
            for (int half = 0; half < 2; half++) {
                const int m = mrow + half * 8;
                float2 v = half ? make_float2(acc[mt][nt][2], acc[mt][nt][3])
                                : make_float2(acc[mt][nt][0], acc[mt][nt][1]);
                if (bias)  { v.x += bias[ncol]; v.y += bias[ncol + 1]; }
                if (resid) {
                    float2 rr = *(const float2*)(resid + (size_t)m * N + ncol);
                    v.x += rr.x; v.y += rr.y;
                }
                *(float2*)(C + (size_t)m * N + ncol) = v;
            }
        }
    }
}

// ======== merged q/k/v projection: one launch, grid (24, 32), bf16 out =====
// blockIdx.x: [0,8)=q, [8,16)=k, [16,24)=v.  v gets bias bv.
__global__ __launch_bounds__(256)
void hmma1b_qkv_kernel(const __nv_bfloat16* __restrict__ Ap, const __nv_bfloat16* __restrict__ wb,
                       const float* __restrict__ bv,
                       __nv_bfloat16* __restrict__ qb, __nv_bfloat16* __restrict__ kb,
                       __nv_bfloat16* __restrict__ vb)
{
    extern __shared__ __align__(1024) char smem[];
    const uint32_t sb = smem_to_u32(smem);

    const int tid = threadIdx.x;
    const int wid = tid >> 5;
    const int lane = tid & 31;
    const int wsel = blockIdx.x >> 3;                 // 0=q 1=k 2=v
    const int n0 = (blockIdx.x & 7) * 128;
    const int m0 = blockIdx.y * 128;
    const int warp_m = wid >> 2;
    const int warp_n = wid & 3;

    const float* bias = (wsel == 2) ? bv : nullptr;
    __nv_bfloat16* C = (wsel == 0) ? qb : (wsel == 1) ? kb : vb;

    const __nv_bfloat16* A_b = Ap + (size_t)m0 * DKK;
    const __nv_bfloat16* B_b = wb + (size_t)wsel * 1024 * 1024 + (size_t)n0 * DKK;

    float acc[4][4][4];
#pragma unroll
    for (int mt = 0; mt < 4; mt++)
#pragma unroll
        for (int nt = 0; nt < 4; nt++)
#pragma unroll
            for (int e = 0; e < 4; e++) acc[mt][nt][e] = 0.f;

    int cso[4];
    size_t cgi[4];
#pragma unroll
    for (int r = 0; r < 4; r++) {
        const int chunk = tid + 256 * r;
        const int row = chunk >> 3;
        const int cc = chunk & 7;
        cso[r] = row * 128 + ((cc * 16) ^ ((row & 7) << 4));
        cgi[r] = (size_t)row * DKK + cc * 8;
    }

    const int rowA = warp_m * 64 + (lane & 15);
    const int colA = ((lane >> 4) << 4);
    const uint32_t maskA = (rowA & 7) << 4;
    const int rowB = warp_n * 32 + (lane & 7);
    const int colB = ((lane >> 3) & 1) << 4;
    const uint32_t maskB = (rowB & 7) << 4;

    {
        const uint32_t st = sb;
#pragma unroll
        for (int r = 0; r < 4; r++) {
            cp16(st + P1_A + cso[r], A_b + cgi[r]);
            cp16(st + P1_B + cso[r], B_b + cgi[r]);
        }
        CP_COMMIT();
    }

    for (int s = 0; s < P1_NST; s++) {
        if (s + 1 < P1_NST) {
            const uint32_t st = sb + ((s + 1) & 1) * P1_STAGE;
            const size_t koff = (size_t)(s + 1) * 64;
#pragma unroll
            for (int r = 0; r < 4; r++) {
                cp16(st + P1_A + cso[r], A_b + cgi[r] + koff);
                cp16(st + P1_B + cso[r], B_b + cgi[r] + koff);
            }
            CP_COMMIT();
            CP_WAIT1();
        } else {
            CP_WAIT0();
        }
        __syncthreads();

        const uint32_t st = sb + (s & 1) * P1_STAGE;
#pragma unroll
        for (int ks = 0; ks < 4; ks++) {
            const int k0b = ks * 32;
            uint32_t Af[4][4], Bf[4][2];
#pragma unroll
            for (int mt = 0; mt < 4; mt++)
                ldsm_x4(Af[mt], st + P1_A + (uint32_t)((rowA + mt * 16) * 128) + (uint32_t)((k0b + colA) ^ maskA));
#pragma unroll
            for (int nt = 0; nt < 4; nt++)
                ldsm_x2(Bf[nt], st + P1_B + (uint32_t)((rowB + nt * 8) * 128) + (uint32_t)((k0b + colB) ^ maskB));
#pragma unroll
            for (int mt = 0; mt < 4; mt++)
#pragma unroll
                for (int nt = 0; nt < 4; nt++)
                    mma_bf16(acc[mt][nt], Af[mt], Bf[nt]);
        }
        __syncthreads();
    }

    const int r0 = lane >> 2;
    const int c0 = (lane & 3) * 2;
#pragma unroll
    for (int mt = 0; mt < 4; mt++) {
        const int mrow = m0 + warp_m * 64 + mt * 16 + r0;
#pragma unroll
        for (int nt = 0; nt < 4; nt++) {
            const int ncol = n0 + warp_n * 32 + nt * 8 + c0;
            float b0 = 0.f, b1 = 0.f;
            if (bias) { b0 = bias[ncol]; b1 = bias[ncol + 1]; }
#pragma unroll
            for (int half = 0; half < 2; half++) {
                const int m = mrow + half * 8;
                float vx = (half ? acc[mt][nt][2] : acc[mt][nt][0]) + b0;
                float vy = (half ? acc[mt][nt][3] : acc[mt][nt][1]) + b1;
                *(uint32_t*)(C + (size_t)m * DKK + ncol) =
                    pack2(__float2bfloat16(vx), __float2bfloat16(vy));
            }
        }
    }
}

// ======================= prep q (fold mixing*scale, bf16 in/out) ===========
__global__ __launch_bounds__(256)
void prep_q_kernel(const __nv_bfloat16* __restrict__ q, const float* __restrict__ mixing,
                   __nv_bfloat16* __restrict__ qm)
{
    const int bh = blockIdx.y;
    const int b = bh >> 4, h = bh & 15;
    const size_t i4 = (size_t)blockIdx.x * 256 + threadIdx.x;
    const int s = (int)(i4 >> 8);
    const int c4 = (int)(i4 & 255);
    uint2 qv = *(const uint2*)(q + ((size_t)b * SS + s) * DKK + c4 * 4);
    float2 q0 = bf2_to_f2(qv.x), q1 = bf2_to_f2(qv.y);
    float4 m = *(const float4*)(mixing + (size_t)h * DKK + c4 * 4);
    q0.x *= m.x * SCALE; q0.y *= m.y * SCALE;
    q1.x *= m.z * SCALE; q1.y *= m.w * SCALE;
    uint2 p;
    p.x = pack2(__float2bfloat16(q0.x), __float2bfloat16(q0.y));
    p.y = pack2(__float2bfloat16(q1.x), __float2bfloat16(q1.y));
    *(uint2*)(qm + ((size_t)bh * SS + s) * DKK + c4 * 4) = p;
}

// ======================= prep V^T per head (bf16 in) =======================
__global__ __launch_bounds__(256)
void prep_vt_kernel(const __nv_bfloat16* __restrict__ v, __nv_bfloat16* __restrict__ vt)
{
    const int tid = threadIdx.x;
    const int bh = blockIdx.z;
    const int b = bh >> 4, h = bh & 15;
    const int j = blockIdx.x * 64 + (tid & 63);
    const int vvg = blockIdx.y * 4 + (tid >> 6);
    uint2 v4 = *(const uint2*)(v + ((size_t)b * SS + j) * DVV + h * HEADV + vvg * 4);
    __nv_bfloat16 e0 = __ushort_as_bfloat16((unsigned short)(v4.x & 0xffffu));
    __nv_bfloat16 e1 = __ushort_as_bfloat16((unsigned short)(v4.x >> 16));
    __nv_bfloat16 e2 = __ushort_as_bfloat16((unsigned short)(v4.y & 0xffffu));
    __nv_bfloat16 e3 = __ushort_as_bfloat16((unsigned short)(v4.y >> 16));
    const size_t ob = ((size_t)bh * HEADV + vvg * 4) * SS + j;
    vt[ob + 0 * SS] = e0;
    vt[ob + 1 * SS] = e1;
    vt[ob + 2 * SS] = e2;
    vt[ob + 3 * SS] = e3;
}

// ======================= phase 1: QK + local softmax + PV ==================
#define SC_A  0
#define SC_B  16384
#define SC_STAGE 49152
#define SC_NST 16
#define FL_P   0
#define FL_V   65536
#define FL_STAT 98304
#define FL_M    100352
#define FL_L    100864
#define FL_SMEM 101376

__global__ __launch_bounds__(256, 1)
void flash1_kernel(const __nv_bfloat16* __restrict__ qm, const __nv_bfloat16* __restrict__ kb,
                   const float* __restrict__ cbt, const __nv_bfloat16* __restrict__ vt,
                   __nv_bfloat16* __restrict__ part, float* __restrict__ pm, float* __restrict__ pl)
{
    extern __shared__ __align__(1024) char smem[];
    const uint32_t sb = smem_to_u32(smem);
    float* sm_stat = (float*)(smem + FL_STAT);
    float* sm_m    = (float*)(smem + FL_M);
    float* sm_l    = (float*)(smem + FL_L);

    const int tid = threadIdx.x;
    const int wid = tid >> 5;
    const int lane = tid & 31;
    const int jc = blockIdx.x;
    const int iblk = blockIdx.y;
    const int bh = blockIdx.z;
    const int b = bh >> 4;
    const int i0 = iblk * 128;
    const int j0 = jc * 256;
    const int warp_m = wid >> 2;
    const int warp_n = wid & 3;

    const __nv_bfloat16* qm_b = qm + ((size_t)bh * SS + i0) * DKK;
    const __nv_bfloat16* kb_b = kb + ((size_t)b * SS + j0) * DKK;

    float acc[4][8][4];
#pragma unroll
    for (int mt = 0; mt < 4; mt++)
#pragma unroll
        for (int nn = 0; nn < 8; nn++)
#pragma unroll
            for (int e = 0; e < 4; e++) acc[mt][nn][e] = 0.f;

    int csoA[4];  size_t cgiA[4];
#pragma unroll
    for (int r = 0; r < 4; r++) {
        const int chunk = tid + 256 * r;
        const int row = chunk >> 3, cc = chunk & 7;
        csoA[r] = row * 128 + ((cc * 16) ^ ((row & 7) << 4));
        cgiA[r] = (size_t)row * DKK + cc * 8;
    }
    int csoB[8];  size_t cgiB[8];
#pragma unroll
    for (int r = 0; r < 8; r++) {
        const int chunk = tid + 256 * r;
        const int row = chunk >> 3, cc = chunk & 7;
        csoB[r] = row * 128 + ((cc * 16) ^ ((row & 7) << 4));
        cgiB[r] = (size_t)row * DKK + cc * 8;
    }

    // ---- QK^T mainloop ---------------------------------------------------
    {
        const uint32_t st = sb;
#pragma unroll
        for (int r = 0; r < 4; r++)
            cp16(st + SC_A + csoA[r], qm_b + cgiA[r]);
#pragma unroll
        for (int r = 0; r < 8; r++)
            cp16(st + SC_B + csoB[r], kb_b + cgiB[r]);
        CP_COMMIT();
    }

    for (int s = 0; s < SC_NST; s++) {
        if (s + 1 < SC_NST) {
            const uint32_t st = sb + ((s + 1) & 1) * SC_STAGE;
            const size_t koff = (size_t)(s + 1) * 64;
#pragma unroll
            for (int r = 0; r < 4; r++)
                cp16(st + SC_A + csoA[r], qm_b + cgiA[r] + koff);
#pragma unroll
            for (int r = 0; r < 8; r++)
                cp16(st + SC_B + csoB[r], kb_b + cgiB[r] + koff);
            CP_COMMIT();
            CP_WAIT1();
        } else {
            CP_WAIT0();
        }
        __syncthreads();

        const uint32_t st = sb + (s & 1) * SC_STAGE;
#pragma unroll
        for (int ks = 0; ks < 4; ks++) {
            const int k0b = ks * 32;
            uint32_t Af[4][4];
#pragma unroll
            for (int mt = 0; mt < 4; mt++) {
                const int rowA = warp_m * 64 + mt * 16 + (lane & 15);
                const uint32_t cA = (uint32_t)((k0b + ((lane >> 4) << 4)) ^ ((rowA & 7) << 4));
                ldsm_x4(Af[mt], st + SC_A + (uint32_t)(rowA * 128) + cA);
            }
#pragma unroll
            for (int ng = 0; ng < 4; ng++) {
                const int rowB = warp_n * 64 + ng * 16 + (lane & 7) + ((lane & 16) >> 1);
                const uint32_t cB = (uint32_t)((k0b + (((lane >> 3) & 1) << 4)) ^ ((rowB & 7) << 4));
                uint32_t B4[4];
                ldsm_x4(B4, st + SC_B + (uint32_t)(rowB * 128) + cB);
#pragma unroll
                for (int mt = 0; mt < 4; mt++) {
                    mma_bf16(acc[mt][ng * 2 + 0], Af[mt], B4 + 0);
                    mma_bf16(acc[mt][ng * 2 + 1], Af[mt], B4 + 2);
                }
            }
        }
        __syncthreads();
    }

    // ---- V prefetch into freed stage smem --------------------------------
#pragma unroll
    for (int c = 0; c < 2; c++) {
#pragma unroll
        for (int r = 0; r < 4; r++) {
            const int id = tid + 256 * r;
            const int row = id >> 4, cc = id & 15;
            const uint32_t so = (uint32_t)(row * 256 + ((cc * 16) ^ ((row & 7) << 4)));
            const size_t gi = ((size_t)bh * HEADV + row) * SS + j0 + c * 128 + cc * 8;
            cp16(sb + FL_V + c * 16384 + so, vt + gi);
        }
    }
    CP_COMMIT();

    // ---- add content bias, row max ---------------------------------------
    const float* cbp = cbt + (size_t)bh * SS + j0;
    float rmax[8];
#pragma unroll
    for (int i = 0; i < 8; i++) rmax[i] = -INFINITY;
#pragma unroll
    for (int nn = 0; nn < 8; nn++) {
        float2 cb2 = *(const float2*)(cbp + warp_n * 64 + nn * 8 + (lane & 3) * 2);
#pragma unroll
        for (int mt = 0; mt < 4; mt++) {
            acc[mt][nn][0] += cb2.x; acc[mt][nn][1] += cb2.y;
            acc[mt][nn][2] += cb2.x; acc[mt][nn][3] += cb2.y;
            rmax[mt * 2 + 0] = fmaxf(rmax[mt * 2 + 0], fmaxf(acc[mt][nn][0], acc[mt][nn][1]));
            rmax[mt * 2 + 1] = fmaxf(rmax[mt * 2 + 1], fmaxf(acc[mt][nn][2], acc[mt][nn][3]));
        }
    }
#pragma unroll
    for (int i = 0; i < 8; i++) {
        rmax[i] = fmaxf(rmax[i], __shfl_xor_sync(0xffffffffu, rmax[i], 1));
        rmax[i] = fmaxf(rmax[i], __shfl_xor_sync(0xffffffffu, rmax[i], 2));
    }
    if ((lane & 3) == 0) {
#pragma unroll
        for (int mt = 0; mt < 4; mt++) {
            const int r = warp_m * 64 + mt * 16 + (lane >> 2);
            sm_stat[(r + 0) * 4 + warp_n] = rmax[mt * 2 + 0];
            sm_stat[(r + 8) * 4 + warp_n] = rmax[mt * 2 + 1];
        }
    }
    __syncthreads();
    if (tid < 128) {
        sm_m[tid] = fmaxf(fmaxf(sm_stat[tid * 4 + 0], sm_stat[tid * 4 + 1]),
                          fmaxf(sm_stat[tid * 4 + 2], sm_stat[tid * 4 + 3]));
    }
    __syncthreads();

    // ---- exp, P store (512B pitch), partial sums -------------------------
    float rsum[8];
#pragma unroll
    for (int i = 0; i < 8; i++) rsum[i] = 0.f;
#pragma unroll
    for (int mt = 0; mt < 4; mt++) {
        const int r0 = warp_m * 64 + mt * 16 + (lane >> 2);
        const float mn0 = sm_m[r0];
        const float mn1 = sm_m[r0 + 8];
        const uint32_t off0base = (uint32_t)(r0 * 512);
        const uint32_t off1base = (uint32_t)((r0 + 8) * 512);
        const uint32_t mask0 = (uint32_t)((r0 & 7) << 4);
        const uint32_t mask1 = (uint32_t)(((r0 + 8) & 7) << 4);
#pragma unroll
        for (int nn = 0; nn < 8; nn++) {
            float p0 = __expf(acc[mt][nn][0] - mn0);
            float p1 = __expf(acc[mt][nn][1] - mn0);
            float p2 = __expf(acc[mt][nn][2] - mn1);
            float p3 = __expf(acc[mt][nn][3] - mn1);
            rsum[mt * 2 + 0] += p0 + p1;
            rsum[mt * 2 + 1] += p2 + p3;
            const uint32_t colbyte = (uint32_t)((warp_n * 64 + nn * 8 + (lane & 3) * 2) * 2);
            *(uint32_t*)(smem + FL_P + off0base + (colbyte ^ mask0)) = pack2(__float2bfloat16(p0), __float2bfloat16(p1));
            *(uint32_t*)(smem + FL_P + off1base + (colbyte ^ mask1)) = pack2(__float2bfloat16(p2), __float2bfloat16(p3));
        }
    }
#pragma unroll
    for (int i = 0; i < 8; i++) {
        rsum[i] += __shfl_xor_sync(0xffffffffu, rsum[i], 1);
        rsum[i] += __shfl_xor_sync(0xffffffffu, rsum[i], 2);
    }
    if ((lane & 3) == 0) {
#pragma unroll
        for (int mt = 0; mt < 4; mt++) {
            const int r = warp_m * 64 + mt * 16 + (lane >> 2);
            sm_stat[(r + 0) * 4 + warp_n] = rsum[mt * 2 + 0];
            sm_stat[(r + 8) * 4 + warp_n] = rsum[mt * 2 + 1];
        }
    }
    __syncthreads();
    if (tid < 128) {
        sm_l[tid] = sm_stat[tid * 4 + 0] + sm_stat[tid * 4 + 1]
                  + sm_stat[tid * 4 + 2] + sm_stat[tid * 4 + 3];
    }
    CP_WAIT0();
    __syncthreads();

    // ---- PV: O = P(128x256) @ V^T ----------------------------------------
    float O[8][4];
#pragma unroll
    for (int nn = 0; nn < 8; nn++)
#pragma unroll
        for (int e = 0; e < 4; e++) O[nn][e] = 0.f;

    const int m0w = wid * 16;
#pragma unroll
    for (int ks = 0; ks < 16; ks++) {
        const int chunk = ks >> 3;
        const int k0b = (ks & 7) * 32;
        uint32_t P4[4];
        const int rowa = m0w + (lane & 15);
        const uint32_t cA = (uint32_t)((ks * 32 + ((lane >> 4) << 4)) ^ ((rowa & 7) << 4));
        ldsm_x4(P4, sb + FL_P + (uint32_t)(rowa * 512) + cA);
        const uint32_t vbase = sb + FL_V + chunk * 16384;
#pragma unroll
        for (int ng = 0; ng < 4; ng++) {
            const int rowb = ng * 16 + (lane & 7) + ((lane & 16) >> 1);
            const uint32_t cB = (uint32_t)((k0b + (((lane >> 3) & 1) << 4)) ^ ((rowb & 7) << 4));
            uint32_t V4[4];
            ldsm_x4(V4, vbase + (uint32_t)(rowb * 256) + cB);
            mma_bf16(O[ng * 2 + 0], P4, V4 + 0);
            mma_bf16(O[ng * 2 + 1], P4, V4 + 2);
        }
    }

    // ---- write partial O (bf16) + stats ----------------------------------
    const size_t slot = ((size_t)bh * 16 + iblk) * NJC + jc;
    __nv_bfloat16* pbase = part + slot * (128 * 64);
    const int r0 = m0w + (lane >> 2);
    const int r1 = r0 + 8;
    const int c0 = (lane & 3) * 2;
#pragma unroll
    for (int nn = 0; nn < 8; nn++) {
        const int col = nn * 8 + c0;
        *(uint32_t*)(pbase + (size_t)r0 * 64 + col) = pack2(__float2bfloat16(O[nn][0]), __float2bfloat16(O[nn][1]));
        *(uint32_t*)(pbase + (size_t)r1 * 64 + col) = pack2(__float2bfloat16(O[nn][2]), __float2bfloat16(O[nn][3]));
    }
    if (tid < 128) {
        pm[slot * 128 + tid] = sm_m[tid];
        pl[slot * 128 + tid] = sm_l[tid];
    }
}

// ======================= phase 2: combine partials =========================
__global__ __launch_bounds__(256)
void combine_kernel(const __nv_bfloat16* __restrict__ part, const float* __restrict__ pm,
                    const float* __restrict__ pl, __nv_bfloat16* __restrict__ cxb)
{
    const int tid = threadIdx.x;
    const int iblk = blockIdx.x;
    const int bh = blockIdx.y;
    const int b = bh >> 4, h = bh & 15;
    const int row = tid >> 1;
    const int colh = (tid & 1) * 32;

    const size_t slot0 = ((size_t)bh * 16 + iblk) * NJC;

    float mj[NJC], w[NJC];
    float m = -INFINITY;
#pragma unroll
    for (int j = 0; j < NJC; j++) {
        mj[j] = pm[(slot0 + j) * 128 + row];
        m = fmaxf(m, mj[j]);
    }
    float lsum = 0.f;
#pragma unroll
    for (int j = 0; j < NJC; j++) {
        w[j] = __expf(mj[j] - m);
        lsum += pl[(slot0 + j) * 128 + row] * w[j];
    }
    const float inv = 1.f / lsum;

    float o[32];
#pragma unroll
    for (int c = 0; c < 32; c++) o[c] = 0.f;
#pragma unroll
    for (int j = 0; j < NJC; j++) {
        const __nv_bfloat16* pb = part + (slot0 + j) * (128 * 64) + (size_t)row * 64 + colh;
        const float wj = w[j];
#pragma unroll
        for (int c8 = 0; c8 < 4; c8++) {
            uint4 u = *(const uint4*)(pb + c8 * 8);
            float2 f0 = bf2_to_f2(u.x), f1 = bf2_to_f2(u.y);
            float2 f2 = bf2_to_f2(u.z), f3 = bf2_to_f2(u.w);
            o[c8 * 8 + 0] += wj * f0.x; o[c8 * 8 + 1] += wj * f0.y;
            o[c8 * 8 + 2] += wj * f1.x; o[c8 * 8 + 3] += wj * f1.y;
            o[c8 * 8 + 4] += wj * f2.x; o[c8 * 8 + 5] += wj * f2.y;
            o[c8 * 8 + 6] += wj * f3.x; o[c8 * 8 + 7] += wj * f3.y;
        }
    }

    __nv_bfloat16* ob = cxb + ((size_t)b * SS + iblk * 128 + row) * DVV + h * HEADV + colh;
#pragma unroll
    for (int c2 = 0; c2 < 16; c2++) {
        *(uint32_t*)(ob + c2 * 2) =
            pack2(__float2bfloat16(o[c2 * 2] * inv), __float2bfloat16(o[c2 * 2 + 1] * inv));
    }
}

// ======================= LayerNorm =========================================
__global__ __launch_bounds__(256)
void ln_kernel(const float* __restrict__ res, const float* __restrict__ gamma,
               const float* __restrict__ beta, float* __restrict__ out)
{
    const int row = blockIdx.x;
    const int c = threadIdx.x * 4;
    const float4 v = *(const float4*)(res + (size_t)row * DOUT + c);
    float s  = v.x + v.y + v.z + v.w;
    float s2 = v.x * v.x + v.y * v.y + v.z * v.z + v.w * v.w;
#pragma unroll
    for (int o = 16; o >= 1; o >>= 1) {
        s  += __shfl_xor_sync(0xffffffffu, s,  o);
        s2 += __shfl_xor_sync(0xffffffffu, s2, o);
    }
    __shared__ float sh[8], sh2[8];
    __shared__ float mu_s, inv_s;
    const int w = threadIdx.x >> 5;
    if ((threadIdx.x & 31) == 0) { sh[w] = s; sh2[w] = s2; }
    __syncthreads();
    if (threadIdx.x == 0) {
        float S = 0.f, S2 = 0.f;
#pragma unroll
        for (int i = 0; i < 8; i++) { S += sh[i]; S2 += sh2[i]; }
        const float mu = S * (1.f / DOUT);
        const float var = S2 * (1.f / DOUT) - mu * mu;
        mu_s = mu; inv_s = rsqrtf(var + LN_EPS);
    }
    __syncthreads();
    const float mu = mu_s, inv = inv_s;
    const float4 g  = *(const float4*)(gamma + c);
    const float4 bt = *(const float4*)(beta + c);
    float4 o;
    o.x = (v.x - mu) * inv * g.x + bt.x;
    o.y = (v.y - mu) * inv * g.y + bt.y;
    o.z = (v.z - mu) * inv * g.z + bt.z;
    o.w = (v.w - mu) * inv * g.w + bt.w;
    *(float4*)(out + (size_t)row * DOUT + c) = o;
}

// ===========================================================================
extern "C" void kernel_launch(void* const* d_in, const int* in_sizes, int n_in,
                              void* d_out, int out_size)
{
    const float* x      = (const float*)d_in[0];
    const float* Wq     = (const float*)d_in[1];
    const float* Wk     = (const float*)d_in[2];
    const float* Wcb    = (const float*)d_in[3];
    const float* Wv     = (const float*)d_in[4];
    const float* bv     = (const float*)d_in[5];
    const float* mixing = (const float*)d_in[6];
    const float* Wd     = (const float*)d_in[7];
    const float* bd     = (const float*)d_in[8];
    const float* gamma  = (const float*)d_in[9];
    const float* beta   = (const float*)d_in[10];
    float* out = (float*)d_out;

    float *res, *cbt, *pmv, *plv;
    __nv_bfloat16 *part, *qm, *qb, *kb, *vb, *xb, *wb, *vt, *cxb;
    cudaGetSymbolAddress((void**)&res,  g_res);
    cudaGetSymbolAddress((void**)&cbt,  g_cbt);
    cudaGetSymbolAddress((void**)&part, g_part);
    cudaGetSymbolAddress((void**)&pmv,  g_pm);
    cudaGetSymbolAddress((void**)&plv,  g_pl);
    cudaGetSymbolAddress((void**)&qm,   g_qm);
    cudaGetSymbolAddress((void**)&qb,   g_qb);
    cudaGetSymbolAddress((void**)&kb,   g_kb);
    cudaGetSymbolAddress((void**)&vb,   g_vb);
    cudaGetSymbolAddress((void**)&xb,   g_xb);
    cudaGetSymbolAddress((void**)&wb,   g_wb);
    cudaGetSymbolAddress((void**)&vt,   g_vt);
    cudaGetSymbolAddress((void**)&cxb,  g_cxb);

    cudaFuncSetAttribute(flash1_kernel,     cudaFuncAttributeMaxDynamicSharedMemorySize, FL_SMEM);
    cudaFuncSetAttribute(hmma1_nt_kernel,   cudaFuncAttributeMaxDynamicSharedMemorySize, 2 * P1_STAGE);
    cudaFuncSetAttribute(hmma1b_qkv_kernel, cudaFuncAttributeMaxDynamicSharedMemorySize, 2 * P1_STAGE);

    // converts (fp32 -> bf16): x + all 4 weights (one launch)
    cvt_bf_kernel<<<MROWS * DIN / 1024, 256>>>(x, xb);
    cvt_w4_kernel<<<dim3(1024, 4), 256>>>(Wq, Wk, Wv, Wd, wb);

    // merged q/k/v projection (one launch, 768 CTAs)
    hmma1b_qkv_kernel<<<dim3(24, MROWS / 128), 256, 2 * P1_STAGE>>>(xb, wb, bv, qb, kb, vb);
    cb_kernel<<<MROWS / 16, 256>>>(x, Wcb, cbt);

    // attention preps
    prep_q_kernel<<<dim3(SS * DKK / 4 / 256, BH), 256>>>(qb, mixing, qm);
    prep_vt_kernel<<<dim3(SS / 64, HEADV / 16, BH), 256>>>(vb, vt);

    // attention: split-K flash (phase 1) + combine (phase 2)
    flash1_kernel<<<dim3(NJC, SS / 128, BH), 256, FL_SMEM>>>(qm, kb, cbt, vt, part, pmv, plv);
    combine_kernel<<<dim3(SS / 128, BH), 256>>>(part, pmv, plv, cxb);

    // output projection + residual + LN
    hmma1_nt_kernel<<<dim3(DKK / 128, MROWS / 128), 256, 2 * P1_STAGE>>>(cxb, wb + 3ull * 1024 * 1024, bd, x, res, DOUT);
    ln_kernel<<<MROWS, 256>>>(res, gamma, beta, out);
}

// round 17
// speedup vs baseline: 1.1838x; 1.0854x over previous
#include <cuda_runtime.h>
#include <cuda_bf16.h>
#include <math.h>
#include <stdint.h>

// Problem constants
#define BB 2
#define SS 2048
#define DIN 1024
#define HH 16
#define DKK 1024
#define DVV 1024
#define DOUT 1024
#define MROWS (BB*SS)          // 4096
#define BH (BB*HH)             // 32
#define HEADV 64
#define SCALE 0.125f
#define LN_EPS 1e-5f
#define NJC 8                  // j-chunks of 256

// Scratch
__device__ float g_res[(size_t)MROWS * DOUT];
__device__ float g_cbt[(size_t)BH * SS];
__device__ __nv_bfloat16 g_part[(size_t)BH * 16 * NJC * 128 * 64];  // 64 MB
__device__ float g_pm[(size_t)BH * 16 * NJC * 128];
__device__ float g_pl[(size_t)BH * 16 * NJC * 128];
__device__ __nv_bfloat16 g_qm[(size_t)BH * SS * DKK];
__device__ __nv_bfloat16 g_qb[(size_t)MROWS * DKK];
__device__ __nv_bfloat16 g_kb[(size_t)MROWS * DKK];
__device__ __nv_bfloat16 g_vb[(size_t)MROWS * DVV];
__device__ __nv_bfloat16 g_xb[(size_t)MROWS * DIN];
__device__ __nv_bfloat16 g_wb[(size_t)5 * 1024 * 1024];   // Wq,Wk,Wv,Wd + Wcb(padded 128x1024)
__device__ __nv_bfloat16 g_vt[(size_t)BH * HEADV * SS];
__device__ __nv_bfloat16 g_cxb[(size_t)MROWS * DVV];

// ======================= helpers ===========================================
__device__ __forceinline__ uint32_t smem_to_u32(const void* p) {
    uint32_t a;
    asm("{ .reg .u64 t; cvta.to.shared.u64 t, %1; cvt.u32.u64 %0, t; }" : "=r"(a) : "l"(p));
    return a;
}
__device__ __forceinline__ void cp16(uint32_t s, const void* g) {
    asm volatile("cp.async.cg.shared.global [%0], [%1], 16;" :: "r"(s), "l"(g));
}
#define CP_COMMIT() asm volatile("cp.async.commit_group;" ::: "memory")
#define CP_WAIT1()  asm volatile("cp.async.wait_group 1;" ::: "memory")
#define CP_WAIT0()  asm volatile("cp.async.wait_group 0;" ::: "memory")

__device__ __forceinline__ void ldsm_x4(uint32_t* r, uint32_t addr) {
    asm volatile("ldmatrix.sync.aligned.m8n8.x4.shared.b16 {%0,%1,%2,%3}, [%4];"
        : "=r"(r[0]), "=r"(r[1]), "=r"(r[2]), "=r"(r[3]) : "r"(addr));
}
__device__ __forceinline__ void ldsm_x2(uint32_t* r, uint32_t addr) {
    asm volatile("ldmatrix.sync.aligned.m8n8.x2.shared.b16 {%0,%1}, [%2];"
        : "=r"(r[0]), "=r"(r[1]) : "r"(addr));
}
__device__ __forceinline__ void mma_bf16(float* c, const uint32_t* a, const uint32_t* b) {
    asm volatile("mma.sync.aligned.m16n8k16.row.col.f32.bf16.bf16.f32 "
        "{%0,%1,%2,%3}, {%4,%5,%6,%7}, {%8,%9}, {%0,%1,%2,%3};"
        : "+f"(c[0]), "+f"(c[1]), "+f"(c[2]), "+f"(c[3])
        : "r"(a[0]), "r"(a[1]), "r"(a[2]), "r"(a[3]), "r"(b[0]), "r"(b[1]));
}
__device__ __forceinline__ uint32_t pack2(__nv_bfloat16 a, __nv_bfloat16 b) {
    return (uint32_t)__bfloat16_as_ushort(a) | ((uint32_t)__bfloat16_as_ushort(b) << 16);
}
__device__ __forceinline__ float2 bf2_to_f2(uint32_t u) {
    float2 r;
    r.x = __bfloat162float(__ushort_as_bfloat16((unsigned short)(u & 0xffffu)));
    r.y = __bfloat162float(__ushort_as_bfloat16((unsigned short)(u >> 16)));
    return r;
}

// ======================= fp32 -> bf16 converts =============================
__global__ __launch_bounds__(256)
void cvt_bf_kernel(const float* __restrict__ in, __nv_bfloat16* __restrict__ o)
{
    const size_t i4 = (size_t)blockIdx.x * 256 + threadIdx.x;
    float4 v = *(const float4*)(in + i4 * 4);
    uint2 p;
    p.x = pack2(__float2bfloat16(v.x), __float2bfloat16(v.y));
    p.y = pack2(__float2bfloat16(v.z), __float2bfloat16(v.w));
    *(uint2*)(o + i4 * 4) = p;
}

// 4 weights in one launch: blockIdx.y selects source; dst = wb + y*1M
__global__ __launch_bounds__(256)
void cvt_w4_kernel(const float* __restrict__ w0, const float* __restrict__ w1,
                   const float* __restrict__ w2, const float* __restrict__ w3,
                   __nv_bfloat16* __restrict__ wb)
{
    const float* src = (blockIdx.y == 0) ? w0 : (blockIdx.y == 1) ? w1
                     : (blockIdx.y == 2) ? w2 : w3;
    const size_t i4 = (size_t)blockIdx.x * 256 + threadIdx.x;
    float4 v = *(const float4*)(src + i4 * 4);
    uint2 p;
    p.x = pack2(__float2bfloat16(v.x), __float2bfloat16(v.y));
    p.y = pack2(__float2bfloat16(v.z), __float2bfloat16(v.w));
    *(uint2*)(wb + (size_t)blockIdx.y * 1024 * 1024 + i4 * 4) = p;
}

// Wcb (16x1024) -> slot 4, zero-padded to 128x1024
__global__ __launch_bounds__(256)
void cvt_wcb_kernel(const float* __restrict__ wcb, __nv_bfloat16* __restrict__ wb)
{
    const size_t i4 = (size_t)blockIdx.x * 256 + threadIdx.x;   // 128*1024/4 = 32768 chunks -> 128 blocks
    const int row = (int)(i4 >> 8);                              // 4-elem chunks: 256 per row
    uint2 p;
    if (row < 16) {
        float4 v = *(const float4*)(wcb + i4 * 4);
        p.x = pack2(__float2bfloat16(v.x), __float2bfloat16(v.y));
        p.y = pack2(__float2bfloat16(v.z), __float2bfloat16(v.w));
    } else {
        p.x = 0u; p.y = 0u;
    }
    *(uint2*)(wb + (size_t)4 * 1024 * 1024 + i4 * 4) = p;
}

// ======================= 1-pass HMMA NT GEMM, fp32 out (out proj) ==========
#define P1_A 0
#define P1_B 16384
#define P1_STAGE 32768
#define P1_NST 16

__global__ __launch_bounds__(256)
void hmma1_nt_kernel(const __nv_bfloat16* __restrict__ Ap, const __nv_bfloat16* __restrict__ Bp,
                     const float* __restrict__ bias, const float* __restrict__ resid,
                     float* __restrict__ C, int N)
{
    extern __shared__ __align__(1024) char smem[];
    const uint32_t sb = smem_to_u32(smem);

    const int tid = threadIdx.x;
    const int wid = tid >> 5;
    const int lane = tid & 31;
    const int m0 = blockIdx.y * 128;
    const int n0 = blockIdx.x * 128;
    const int warp_m = wid >> 2;
    const int warp_n = wid & 3;

    const __nv_bfloat16* A_b = Ap + (size_t)m0 * DKK;
    const __nv_bfloat16* B_b = Bp + (size_t)n0 * DKK;

    float acc[4][4][4];
#pragma unroll
    for (int mt = 0; mt < 4; mt++)
#pragma unroll
        for (int nt = 0; nt < 4; nt++)
#pragma unroll
            for (int e = 0; e < 4; e++) acc[mt][nt][e] = 0.f;

    int cso[4];
    size_t cgi[4];
#pragma unroll
    for (int r = 0; r < 4; r++) {
        const int chunk = tid + 256 * r;
        const int row = chunk >> 3;
        const int cc = chunk & 7;
        cso[r] = row * 128 + ((cc * 16) ^ ((row & 7) << 4));
        cgi[r] = (size_t)row * DKK + cc * 8;
    }

    const int rowA = warp_m * 64 + (lane & 15);
    const int colA = ((lane >> 4) << 4);
    const uint32_t maskA = (rowA & 7) << 4;
    const int rowB = warp_n * 32 + (lane & 7);
    const int colB = ((lane >> 3) & 1) << 4;
    const uint32_t maskB = (rowB & 7) << 4;

    {
        const uint32_t st = sb;
#pragma unroll
        for (int r = 0; r < 4; r++) {
            cp16(st + P1_A + cso[r], A_b + cgi[r]);
            cp16(st + P1_B + cso[r], B_b + cgi[r]);
        }
        CP_COMMIT();
    }

    for (int s = 0; s < P1_NST; s++) {
        if (s + 1 < P1_NST) {
            const uint32_t st = sb + ((s + 1) & 1) * P1_STAGE;
            const size_t koff = (size_t)(s + 1) * 64;
#pragma unroll
            for (int r = 0; r < 4; r++) {
                cp16(st + P1_A + cso[r], A_b + cgi[r] + koff);
                cp16(st + P1_B + cso[r], B_b + cgi[r] + koff);
            }
            CP_COMMIT();
            CP_WAIT1();
        } else {
            CP_WAIT0();
        }
        __syncthreads();

        const uint32_t st = sb + (s & 1) * P1_STAGE;
#pragma unroll
        for (int ks = 0; ks < 4; ks++) {
            const int k0b = ks * 32;
            uint32_t Af[4][4], Bf[4][2];
#pragma unroll
            for (int mt = 0; mt < 4; mt++)
                ldsm_x4(Af[mt], st + P1_A + (uint32_t)((rowA + mt * 16) * 128) + (uint32_t)((k0b + colA) ^ maskA));
#pragma unroll
            for (int nt = 0; nt < 4; nt++)
                ldsm_x2(Bf[nt], st + P1_B + (uint32_t)((rowB + nt * 8) * 128) + (uint32_t)((k0b + colB) ^ maskB));
#pragma unroll
            for (int mt = 0; mt < 4; mt++)
#pragma unroll
                for (int nt = 0; nt < 4; nt++)
                    mma_bf16(acc[mt][nt], Af[mt], Bf[nt]);
        }
        __syncthreads();
    }

    const int r0 = lane >> 2;
    const int c0 = (lane & 3) * 2;
#pragma unroll
    for (int mt = 0; mt < 4; mt++) {
        const int mrow = m0 + warp_m * 64 + mt * 16 + r0;
#pragma unroll
        for (int nt = 0; nt < 4; nt++) {
            const int ncol = n0 + warp_n * 32 + nt * 8 + c0;
#pragma unroll
            for (int half = 0; half < 2; half++) {
                const int m = mrow + half * 8;
                float2 v = half ? make_float2(acc[mt][nt][2], acc[mt][nt][3])
                                : make_float2(acc[mt][nt][0], acc[mt][nt][1]);
                if (bias)  { v.x += bias[ncol]; v.y += bias[ncol + 1]; }
                if (resid) {
                    float2 rr = *(const float2*)(resid + (size_t)m * N + ncol);
                    v.x += rr.x; v.y += rr.y;
                }
                *(float2*)(C + (size_t)m * N + ncol) = v;
            }
        }
    }
}

// ======== merged q/k/v/cb projection: one launch, grid (25, 32) ============
// blockIdx.x: [0,8)=q, [8,16)=k, [16,24)=v, 24=cb (N=16, writes cbt transposed)
__global__ __launch_bounds__(256)
void hmma1b_qkvc_kernel(const __nv_bfloat16* __restrict__ Ap, const __nv_bfloat16* __restrict__ wb,
                        const float* __restrict__ bv,
                        __nv_bfloat16* __restrict__ qb, __nv_bfloat16* __restrict__ kb,
                        __nv_bfloat16* __restrict__ vb, float* __restrict__ cbt)
{
    extern __shared__ __align__(1024) char smem[];
    const uint32_t sb = smem_to_u32(smem);

    const int tid = threadIdx.x;
    const int wid = tid >> 5;
    const int lane = tid & 31;
    const int wsel = blockIdx.x >> 3;                 // 0=q 1=k 2=v 3=cb
    const int n0 = (blockIdx.x & 7) * 128;
    const int m0 = blockIdx.y * 128;
    const int warp_m = wid >> 2;
    const int warp_n = wid & 3;

    const __nv_bfloat16* A_b = Ap + (size_t)m0 * DKK;
    const size_t woff = (wsel == 3) ? (size_t)4 * 1024 * 1024 : (size_t)wsel * 1024 * 1024;
    const __nv_bfloat16* B_b = wb + woff + (size_t)n0 * DKK;

    float acc[4][4][4];
#pragma unroll
    for (int mt = 0; mt < 4; mt++)
#pragma unroll
        for (int nt = 0; nt < 4; nt++)
#pragma unroll
            for (int e = 0; e < 4; e++) acc[mt][nt][e] = 0.f;

    int cso[4];
    size_t cgi[4];
#pragma unroll
    for (int r = 0; r < 4; r++) {
        const int chunk = tid + 256 * r;
        const int row = chunk >> 3;
        const int cc = chunk & 7;
        cso[r] = row * 128 + ((cc * 16) ^ ((row & 7) << 4));
        cgi[r] = (size_t)row * DKK + cc * 8;
    }

    const int rowA = warp_m * 64 + (lane & 15);
    const int colA = ((lane >> 4) << 4);
    const uint32_t maskA = (rowA & 7) << 4;
    const int rowB = warp_n * 32 + (lane & 7);
    const int colB = ((lane >> 3) & 1) << 4;
    const uint32_t maskB = (rowB & 7) << 4;

    {
        const uint32_t st = sb;
#pragma unroll
        for (int r = 0; r < 4; r++) {
            cp16(st + P1_A + cso[r], A_b + cgi[r]);
            cp16(st + P1_B + cso[r], B_b + cgi[r]);
        }
        CP_COMMIT();
    }

    for (int s = 0; s < P1_NST; s++) {
        if (s + 1 < P1_NST) {
            const uint32_t st = sb + ((s + 1) & 1) * P1_STAGE;
            const size_t koff = (size_t)(s + 1) * 64;
#pragma unroll
            for (int r = 0; r < 4; r++) {
                cp16(st + P1_A + cso[r], A_b + cgi[r] + koff);
                cp16(st + P1_B + cso[r], B_b + cgi[r] + koff);
            }
            CP_COMMIT();
            CP_WAIT1();
        } else {
            CP_WAIT0();
        }
        __syncthreads();

        const uint32_t st = sb + (s & 1) * P1_STAGE;
#pragma unroll
        for (int ks = 0; ks < 4; ks++) {
            const int k0b = ks * 32;
            uint32_t Af[4][4], Bf[4][2];
#pragma unroll
            for (int mt = 0; mt < 4; mt++)
                ldsm_x4(Af[mt], st + P1_A + (uint32_t)((rowA + mt * 16) * 128) + (uint32_t)((k0b + colA) ^ maskA));
#pragma unroll
            for (int nt = 0; nt < 4; nt++)
                ldsm_x2(Bf[nt], st + P1_B + (uint32_t)((rowB + nt * 8) * 128) + (uint32_t)((k0b + colB) ^ maskB));
#pragma unroll
            for (int mt = 0; mt < 4; mt++)
#pragma unroll
                for (int nt = 0; nt < 4; nt++)
                    mma_bf16(acc[mt][nt], Af[mt], Bf[nt]);
        }
        __syncthreads();
    }

    const int r0 = lane >> 2;
    const int c0 = (lane & 3) * 2;
    if (wsel < 3) {
        const float* bias = (wsel == 2) ? bv : nullptr;
        __nv_bfloat16* C = (wsel == 0) ? qb : (wsel == 1) ? kb : vb;
#pragma unroll
        for (int mt = 0; mt < 4; mt++) {
            const int mrow = m0 + warp_m * 64 + mt * 16 + r0;
#pragma unroll
            for (int nt = 0; nt < 4; nt++) {
                const int ncol = n0 + warp_n * 32 + nt * 8 + c0;
                float b0 = 0.f, b1 = 0.f;
                if (bias) { b0 = bias[ncol]; b1 = bias[ncol + 1]; }
#pragma unroll
                for (int half = 0; half < 2; half++) {
                    const int m = mrow + half * 8;
                    float vx = (half ? acc[mt][nt][2] : acc[mt][nt][0]) + b0;
                    float vy = (half ? acc[mt][nt][3] : acc[mt][nt][1]) + b1;
                    *(uint32_t*)(C + (size_t)m * DKK + ncol) =
                        pack2(__float2bfloat16(vx), __float2bfloat16(vy));
                }
            }
        }
    } else {
        // cb epilogue: ncol<16 only; write cbt[(b*HH+h)*SS + s] = acc * SCALE
#pragma unroll
        for (int mt = 0; mt < 4; mt++) {
            const int mrow = m0 + warp_m * 64 + mt * 16 + r0;
#pragma unroll
            for (int nt = 0; nt < 4; nt++) {
                const int ncol = warp_n * 32 + nt * 8 + c0;
                if (ncol < 16) {
#pragma unroll
                    for (int half = 0; half < 2; half++) {
                        const int m = mrow + half * 8;
                        const int bb = m >> 11, s = m & 2047;
                        const float vx = (half ? acc[mt][nt][2] : acc[mt][nt][0]) * SCALE;
                        const float vy = (half ? acc[mt][nt][3] : acc[mt][nt][1]) * SCALE;
                        cbt[((size_t)(bb * HH + ncol + 0)) * SS + s] = vx;
                        cbt[((size_t)(bb * HH + ncol + 1)) * SS + s] = vy;
                    }
                }
            }
        }
    }
}

// ======================= prep q (fold mixing*scale, bf16 in/out) ===========
__global__ __launch_bounds__(256)
void prep_q_kernel(const __nv_bfloat16* __restrict__ q, const float* __restrict__ mixing,
                   __nv_bfloat16* __restrict__ qm)
{
    const int bh = blockIdx.y;
    const int b = bh >> 4, h = bh & 15;
    const size_t i4 = (size_t)blockIdx.x * 256 + threadIdx.x;
    const int s = (int)(i4 >> 8);
    const int c4 = (int)(i4 & 255);
    uint2 qv = *(const uint2*)(q + ((size_t)b * SS + s) * DKK + c4 * 4);
    float2 q0 = bf2_to_f2(qv.x), q1 = bf2_to_f2(qv.y);
    float4 m = *(const float4*)(mixing + (size_t)h * DKK + c4 * 4);
    q0.x *= m.x * SCALE; q0.y *= m.y * SCALE;
    q1.x *= m.z * SCALE; q1.y *= m.w * SCALE;
    uint2 p;
    p.x = pack2(__float2bfloat16(q0.x), __float2bfloat16(q0.y));
    p.y = pack2(__float2bfloat16(q1.x), __float2bfloat16(q1.y));
    *(uint2*)(qm + ((size_t)bh * SS + s) * DKK + c4 * 4) = p;
}

// ======================= prep V^T per head (bf16 in) =======================
__global__ __launch_bounds__(256)
void prep_vt_kernel(const __nv_bfloat16* __restrict__ v, __nv_bfloat16* __restrict__ vt)
{
    const int tid = threadIdx.x;
    const int bh = blockIdx.z;
    const int b = bh >> 4, h = bh & 15;
    const int j = blockIdx.x * 64 + (tid & 63);
    const int vvg = blockIdx.y * 4 + (tid >> 6);
    uint2 v4 = *(const uint2*)(v + ((size_t)b * SS + j) * DVV + h * HEADV + vvg * 4);
    __nv_bfloat16 e0 = __ushort_as_bfloat16((unsigned short)(v4.x & 0xffffu));
    __nv_bfloat16 e1 = __ushort_as_bfloat16((unsigned short)(v4.x >> 16));
    __nv_bfloat16 e2 = __ushort_as_bfloat16((unsigned short)(v4.y & 0xffffu));
    __nv_bfloat16 e3 = __ushort_as_bfloat16((unsigned short)(v4.y >> 16));
    const size_t ob = ((size_t)bh * HEADV + vvg * 4) * SS + j;
    vt[ob + 0 * SS] = e0;
    vt[ob + 1 * SS] = e1;
    vt[ob + 2 * SS] = e2;
    vt[ob + 3 * SS] = e3;
}

// ======================= phase 1: QK + local softmax + PV ==================
#define SC_A  0
#define SC_B  16384
#define SC_STAGE 49152
#define SC_NST 16
#define FL_P   0
#define FL_V   65536
#define FL_STAT 98304
#define FL_M    100352
#define FL_L    100864
#define FL_SMEM 101376

__global__ __launch_bounds__(256, 1)
void flash1_kernel(const __nv_bfloat16* __restrict__ qm, const __nv_bfloat16* __restrict__ kb,
                   const float* __restrict__ cbt, const __nv_bfloat16* __restrict__ vt,
                   __nv_bfloat16* __restrict__ part, float* __restrict__ pm, float* __restrict__ pl)
{
    extern __shared__ __align__(1024) char smem[];
    const uint32_t sb = smem_to_u32(smem);
    float* sm_stat = (float*)(smem + FL_STAT);
    float* sm_m    = (float*)(smem + FL_M);
    float* sm_l    = (float*)(smem + FL_L);

    const int tid = threadIdx.x;
    const int wid = tid >> 5;
    const int lane = tid & 31;
    const int jc = blockIdx.x;
    const int iblk = blockIdx.y;
    const int bh = blockIdx.z;
    const int b = bh >> 4;
    const int i0 = iblk * 128;
    const int j0 = jc * 256;
    const int warp_m = wid >> 2;
    const int warp_n = wid & 3;

    const __nv_bfloat16* qm_b = qm + ((size_t)bh * SS + i0) * DKK;
    const __nv_bfloat16* kb_b = kb + ((size_t)b * SS + j0) * DKK;

    float acc[4][8][4];
#pragma unroll
    for (int mt = 0; mt < 4; mt++)
#pragma unroll
        for (int nn = 0; nn < 8; nn++)
#pragma unroll
            for (int e = 0; e < 4; e++) acc[mt][nn][e] = 0.f;

    int csoA[4];  size_t cgiA[4];
#pragma unroll
    for (int r = 0; r < 4; r++) {
        const int chunk = tid + 256 * r;
        const int row = chunk >> 3, cc = chunk & 7;
        csoA[r] = row * 128 + ((cc * 16) ^ ((row & 7) << 4));
        cgiA[r] = (size_t)row * DKK + cc * 8;
    }
    int csoB[8];  size_t cgiB[8];
#pragma unroll
    for (int r = 0; r < 8; r++) {
        const int chunk = tid + 256 * r;
        const int row = chunk >> 3, cc = chunk & 7;
        csoB[r] = row * 128 + ((cc * 16) ^ ((row & 7) << 4));
        cgiB[r] = (size_t)row * DKK + cc * 8;
    }

    // ---- QK^T mainloop ---------------------------------------------------
    {
        const uint32_t st = sb;
#pragma unroll
        for (int r = 0; r < 4; r++)
            cp16(st + SC_A + csoA[r], qm_b + cgiA[r]);
#pragma unroll
        for (int r = 0; r < 8; r++)
            cp16(st + SC_B + csoB[r], kb_b + cgiB[r]);
        CP_COMMIT();
    }

    for (int s = 0; s < SC_NST; s++) {
        if (s + 1 < SC_NST) {
            const uint32_t st = sb + ((s + 1) & 1) * SC_STAGE;
            const size_t koff = (size_t)(s + 1) * 64;
#pragma unroll
            for (int r = 0; r < 4; r++)
                cp16(st + SC_A + csoA[r], qm_b + cgiA[r] + koff);
#pragma unroll
            for (int r = 0; r < 8; r++)
                cp16(st + SC_B + csoB[r], kb_b + cgiB[r] + koff);
            CP_COMMIT();
            CP_WAIT1();
        } else {
            CP_WAIT0();
        }
        __syncthreads();

        const uint32_t st = sb + (s & 1) * SC_STAGE;
#pragma unroll
        for (int ks = 0; ks < 4; ks++) {
            const int k0b = ks * 32;
            uint32_t Af[4][4];
#pragma unroll
            for (int mt = 0; mt < 4; mt++) {
                const int rowA = warp_m * 64 + mt * 16 + (lane & 15);
                const uint32_t cA = (uint32_t)((k0b + ((lane >> 4) << 4)) ^ ((rowA & 7) << 4));
                ldsm_x4(Af[mt], st + SC_A + (uint32_t)(rowA * 128) + cA);
            }
#pragma unroll
            for (int ng = 0; ng < 4; ng++) {
                const int rowB = warp_n * 64 + ng * 16 + (lane & 7) + ((lane & 16) >> 1);
                const uint32_t cB = (uint32_t)((k0b + (((lane >> 3) & 1) << 4)) ^ ((rowB & 7) << 4));
                uint32_t B4[4];
                ldsm_x4(B4, st + SC_B + (uint32_t)(rowB * 128) + cB);
#pragma unroll
                for (int mt = 0; mt < 4; mt++) {
                    mma_bf16(acc[mt][ng * 2 + 0], Af[mt], B4 + 0);
                    mma_bf16(acc[mt][ng * 2 + 1], Af[mt], B4 + 2);
                }
            }
        }
        __syncthreads();
    }

    // ---- V prefetch into freed stage smem --------------------------------
#pragma unroll
    for (int c = 0; c < 2; c++) {
#pragma unroll
        for (int r = 0; r < 4; r++) {
            const int id = tid + 256 * r;
            const int row = id >> 4, cc = id & 15;
            const uint32_t so = (uint32_t)(row * 256 + ((cc * 16) ^ ((row & 7) << 4)));
            const size_t gi = ((size_t)bh * HEADV + row) * SS + j0 + c * 128 + cc * 8;
            cp16(sb + FL_V + c * 16384 + so, vt + gi);
        }
    }
    CP_COMMIT();

    // ---- add content bias, row max ---------------------------------------
    const float* cbp = cbt + (size_t)bh * SS + j0;
    float rmax[8];
#pragma unroll
    for (int i = 0; i < 8; i++) rmax[i] = -INFINITY;
#pragma unroll
    for (int nn = 0; nn < 8; nn++) {
        float2 cb2 = *(const float2*)(cbp + warp_n * 64 + nn * 8 + (lane & 3) * 2);
#pragma unroll
        for (int mt = 0; mt < 4; mt++) {
            acc[mt][nn][0] += cb2.x; acc[mt][nn][1] += cb2.y;
            acc[mt][nn][2] += cb2.x; acc[mt][nn][3] += cb2.y;
            rmax[mt * 2 + 0] = fmaxf(rmax[mt * 2 + 0], fmaxf(acc[mt][nn][0], acc[mt][nn][1]));
            rmax[mt * 2 + 1] = fmaxf(rmax[mt * 2 + 1], fmaxf(acc[mt][nn][2], acc[mt][nn][3]));
        }
    }
#pragma unroll
    for (int i = 0; i < 8; i++) {
        rmax[i] = fmaxf(rmax[i], __shfl_xor_sync(0xffffffffu, rmax[i], 1));
        rmax[i] = fmaxf(rmax[i], __shfl_xor_sync(0xffffffffu, rmax[i], 2));
    }
    if ((lane & 3) == 0) {
#pragma unroll
        for (int mt = 0; mt < 4; mt++) {
            const int r = warp_m * 64 + mt * 16 + (lane >> 2);
            sm_stat[(r + 0) * 4 + warp_n] = rmax[mt * 2 + 0];
            sm_stat[(r + 8) * 4 + warp_n] = rmax[mt * 2 + 1];
        }
    }
    __syncthreads();
    if (tid < 128) {
        sm_m[tid] = fmaxf(fmaxf(sm_stat[tid * 4 + 0], sm_stat[tid * 4 + 1]),
                          fmaxf(sm_stat[tid * 4 + 2], sm_stat[tid * 4 + 3]));
    }
    __syncthreads();

    // ---- exp, P store (512B pitch), partial sums -------------------------
    float rsum[8];
#pragma unroll
    for (int i = 0; i < 8; i++) rsum[i] = 0.f;
#pragma unroll
    for (int mt = 0; mt < 4; mt++) {
        const int r0 = warp_m * 64 + mt * 16 + (lane >> 2);
        const float mn0 = sm_m[r0];
        const float mn1 = sm_m[r0 + 8];
        const uint32_t off0base = (uint32_t)(r0 * 512);
        const uint32_t off1base = (uint32_t)((r0 + 8) * 512);
        const uint32_t mask0 = (uint32_t)((r0 & 7) << 4);
        const uint32_t mask1 = (uint32_t)(((r0 + 8) & 7) << 4);
#pragma unroll
        for (int nn = 0; nn < 8; nn++) {
            float p0 = __expf(acc[mt][nn][0] - mn0);
            float p1 = __expf(acc[mt][nn][1] - mn0);
            float p2 = __expf(acc[mt][nn][2] - mn1);
            float p3 = __expf(acc[mt][nn][3] - mn1);
            rsum[mt * 2 + 0] += p0 + p1;
            rsum[mt * 2 + 1] += p2 + p3;
            const uint32_t colbyte = (uint32_t)((warp_n * 64 + nn * 8 + (lane & 3) * 2) * 2);
            *(uint32_t*)(smem + FL_P + off0base + (colbyte ^ mask0)) = pack2(__float2bfloat16(p0), __float2bfloat16(p1));
            *(uint32_t*)(smem + FL_P + off1base + (colbyte ^ mask1)) = pack2(__float2bfloat16(p2), __float2bfloat16(p3));
        }
    }
#pragma unroll
    for (int i = 0; i < 8; i++) {
        rsum[i] += __shfl_xor_sync(0xffffffffu, rsum[i], 1);
        rsum[i] += __shfl_xor_sync(0xffffffffu, rsum[i], 2);
    }
    if ((lane & 3) == 0) {
#pragma unroll
        for (int mt = 0; mt < 4; mt++) {
            const int r = warp_m * 64 + mt * 16 + (lane >> 2);
            sm_stat[(r + 0) * 4 + warp_n] = rsum[mt * 2 + 0];
            sm_stat[(r + 8) * 4 + warp_n] = rsum[mt * 2 + 1];
        }
    }
    __syncthreads();
    if (tid < 128) {
        sm_l[tid] = sm_stat[tid * 4 + 0] + sm_stat[tid * 4 + 1]
                  + sm_stat[tid * 4 + 2] + sm_stat[tid * 4 + 3];
    }
    CP_WAIT0();
    __syncthreads();

    // ---- PV: O = P(128x256) @ V^T ----------------------------------------
    float O[8][4];
#pragma unroll
    for (int nn = 0; nn < 8; nn++)
#pragma unroll
        for (int e = 0; e < 4; e++) O[nn][e] = 0.f;

    const int m0w = wid * 16;
#pragma unroll
    for (int ks = 0; ks < 16; ks++) {
        const int chunk = ks >> 3;
        const int k0b = (ks & 7) * 32;
        uint32_t P4[4];
        const int rowa = m0w + (lane & 15);
        const uint32_t cA = (uint32_t)((ks * 32 + ((lane >> 4) << 4)) ^ ((rowa & 7) << 4));
        ldsm_x4(P4, sb + FL_P + (uint32_t)(rowa * 512) + cA);
        const uint32_t vbase = sb + FL_V + chunk * 16384;
#pragma unroll
        for (int ng = 0; ng < 4; ng++) {
            const int rowb = ng * 16 + (lane & 7) + ((lane & 16) >> 1);
            const uint32_t cB = (uint32_t)((k0b + (((lane >> 3) & 1) << 4)) ^ ((rowb & 7) << 4));
            uint32_t V4[4];
            ldsm_x4(V4, vbase + (uint32_t)(rowb * 256) + cB);
            mma_bf16(O[ng * 2 + 0], P4, V4 + 0);
            mma_bf16(O[ng * 2 + 1], P4, V4 + 2);
        }
    }

    // ---- write partial O (bf16) + stats ----------------------------------
    const size_t slot = ((size_t)bh * 16 + iblk) * NJC + jc;
    __nv_bfloat16* pbase = part + slot * (128 * 64);
    const int r0 = m0w + (lane >> 2);
    const int r1 = r0 + 8;
    const int c0 = (lane & 3) * 2;
#pragma unroll
    for (int nn = 0; nn < 8; nn++) {
        const int col = nn * 8 + c0;
        *(uint32_t*)(pbase + (size_t)r0 * 64 + col) = pack2(__float2bfloat16(O[nn][0]), __float2bfloat16(O[nn][1]));
        *(uint32_t*)(pbase + (size_t)r1 * 64 + col) = pack2(__float2bfloat16(O[nn][2]), __float2bfloat16(O[nn][3]));
    }
    if (tid < 128) {
        pm[slot * 128 + tid] = sm_m[tid];
        pl[slot * 128 + tid] = sm_l[tid];
    }
}

// ======================= phase 2: combine partials =========================
__global__ __launch_bounds__(256)
void combine_kernel(const __nv_bfloat16* __restrict__ part, const float* __restrict__ pm,
                    const float* __restrict__ pl, __nv_bfloat16* __restrict__ cxb)
{
    const int tid = threadIdx.x;
    const int iblk = blockIdx.x;
    const int bh = blockIdx.y;
    const int b = bh >> 4, h = bh & 15;
    const int row = tid >> 1;
    const int colh = (tid & 1) * 32;

    const size_t slot0 = ((size_t)bh * 16 + iblk) * NJC;

    float mj[NJC], w[NJC];
    float m = -INFINITY;
#pragma unroll
    for (int j = 0; j < NJC; j++) {
        mj[j] = pm[(slot0 + j) * 128 + row];
        m = fmaxf(m, mj[j]);
    }
    float lsum = 0.f;
#pragma unroll
    for (int j = 0; j < NJC; j++) {
        w[j] = __expf(mj[j] - m);
        lsum += pl[(slot0 + j) * 128 + row] * w[j];
    }
    const float inv = 1.f / lsum;

    float o[32];
#pragma unroll
    for (int c = 0; c < 32; c++) o[c] = 0.f;
#pragma unroll
    for (int j = 0; j < NJC; j++) {
        const __nv_bfloat16* pb = part + (slot0 + j) * (128 * 64) + (size_t)row * 64 + colh;
        const float wj = w[j];
#pragma unroll
        for (int c8 = 0; c8 < 4; c8++) {
            uint4 u = *(const uint4*)(pb + c8 * 8);
            float2 f0 = bf2_to_f2(u.x), f1 = bf2_to_f2(u.y);
            float2 f2 = bf2_to_f2(u.z), f3 = bf2_to_f2(u.w);
            o[c8 * 8 + 0] += wj * f0.x; o[c8 * 8 + 1] += wj * f0.y;
            o[c8 * 8 + 2] += wj * f1.x; o[c8 * 8 + 3] += wj * f1.y;
            o[c8 * 8 + 4] += wj * f2.x; o[c8 * 8 + 5] += wj * f2.y;
            o[c8 * 8 + 6] += wj * f3.x; o[c8 * 8 + 7] += wj * f3.y;
        }
    }

    __nv_bfloat16* ob = cxb + ((size_t)b * SS + iblk * 128 + row) * DVV + h * HEADV + colh;
#pragma unroll
    for (int c2 = 0; c2 < 16; c2++) {
        *(uint32_t*)(ob + c2 * 2) =
            pack2(__float2bfloat16(o[c2 * 2] * inv), __float2bfloat16(o[c2 * 2 + 1] * inv));
    }
}

// ======================= LayerNorm =========================================
__global__ __launch_bounds__(256)
void ln_kernel(const float* __restrict__ res, const float* __restrict__ gamma,
               const float* __restrict__ beta, float* __restrict__ out)
{
    const int row = blockIdx.x;
    const int c = threadIdx.x * 4;
    const float4 v = *(const float4*)(res + (size_t)row * DOUT + c);
    float s  = v.x + v.y + v.z + v.w;
    float s2 = v.x * v.x + v.y * v.y + v.z * v.z + v.w * v.w;
#pragma unroll
    for (int o = 16; o >= 1; o >>= 1) {
        s  += __shfl_xor_sync(0xffffffffu, s,  o);
        s2 += __shfl_xor_sync(0xffffffffu, s2, o);
    }
    __shared__ float sh[8], sh2[8];
    __shared__ float mu_s, inv_s;
    const int w = threadIdx.x >> 5;
    if ((threadIdx.x & 31) == 0) { sh[w] = s; sh2[w] = s2; }
    __syncthreads();
    if (threadIdx.x == 0) {
        float S = 0.f, S2 = 0.f;
#pragma unroll
        for (int i = 0; i < 8; i++) { S += sh[i]; S2 += sh2[i]; }
        const float mu = S * (1.f / DOUT);
        const float var = S2 * (1.f / DOUT) - mu * mu;
        mu_s = mu; inv_s = rsqrtf(var + LN_EPS);
    }
    __syncthreads();
    const float mu = mu_s, inv = inv_s;
    const float4 g  = *(const float4*)(gamma + c);
    const float4 bt = *(const float4*)(beta + c);
    float4 o;
    o.x = (v.x - mu) * inv * g.x + bt.x;
    o.y = (v.y - mu) * inv * g.y + bt.y;
    o.z = (v.z - mu) * inv * g.z + bt.z;
    o.w = (v.w - mu) * inv * g.w + bt.w;
    *(float4*)(out + (size_t)row * DOUT + c) = o;
}

// ===========================================================================
extern "C" void kernel_launch(void* const* d_in, const int* in_sizes, int n_in,
                              void* d_out, int out_size)
{
    const float* x      = (const float*)d_in[0];
    const float* Wq     = (const float*)d_in[1];
    const float* Wk     = (const float*)d_in[2];
    const float* Wcb    = (const float*)d_in[3];
    const float* Wv     = (const float*)d_in[4];
    const float* bv     = (const float*)d_in[5];
    const float* mixing = (const float*)d_in[6];
    const float* Wd     = (const float*)d_in[7];
    const float* bd     = (const float*)d_in[8];
    const float* gamma  = (const float*)d_in[9];
    const float* beta   = (const float*)d_in[10];
    float* out = (float*)d_out;

    float *res, *cbt, *pmv, *plv;
    __nv_bfloat16 *part, *qm, *qb, *kb, *vb, *xb, *wb, *vt, *cxb;
    cudaGetSymbolAddress((void**)&res,  g_res);
    cudaGetSymbolAddress((void**)&cbt,  g_cbt);
    cudaGetSymbolAddress((void**)&part, g_part);
    cudaGetSymbolAddress((void**)&pmv,  g_pm);
    cudaGetSymbolAddress((void**)&plv,  g_pl);
    cudaGetSymbolAddress((void**)&qm,   g_qm);
    cudaGetSymbolAddress((void**)&qb,   g_qb);
    cudaGetSymbolAddress((void**)&kb,   g_kb);
    cudaGetSymbolAddress((void**)&vb,   g_vb);
    cudaGetSymbolAddress((void**)&xb,   g_xb);
    cudaGetSymbolAddress((void**)&wb,   g_wb);
    cudaGetSymbolAddress((void**)&vt,   g_vt);
    cudaGetSymbolAddress((void**)&cxb,  g_cxb);

    cudaFuncSetAttribute(flash1_kernel,      cudaFuncAttributeMaxDynamicSharedMemorySize, FL_SMEM);
    cudaFuncSetAttribute(hmma1_nt_kernel,    cudaFuncAttributeMaxDynamicSharedMemorySize, 2 * P1_STAGE);
    cudaFuncSetAttribute(hmma1b_qkvc_kernel, cudaFuncAttributeMaxDynamicSharedMemorySize, 2 * P1_STAGE);

    // converts (fp32 -> bf16): x, 4 weights, Wcb (padded)
    cvt_bf_kernel<<<MROWS * DIN / 1024, 256>>>(x, xb);
    cvt_w4_kernel<<<dim3(1024, 4), 256>>>(Wq, Wk, Wv, Wd, wb);
    cvt_wcb_kernel<<<128, 256>>>(Wcb, wb);

    // merged q/k/v/cb projection (one launch, 800 CTAs)
    hmma1b_qkvc_kernel<<<dim3(25, MROWS / 128), 256, 2 * P1_STAGE>>>(xb, wb, bv, qb, kb, vb, cbt);

    // attention preps
    prep_q_kernel<<<dim3(SS * DKK / 4 / 256, BH), 256>>>(qb, mixing, qm);
    prep_vt_kernel<<<dim3(SS / 64, HEADV / 16, BH), 256>>>(vb, vt);

    // attention: split-K flash (phase 1) + combine (phase 2)
    flash1_kernel<<<dim3(NJC, SS / 128, BH), 256, FL_SMEM>>>(qm, kb, cbt, vt, part, pmv, plv);
    combine_kernel<<<dim3(SS / 128, BH), 256>>>(part, pmv, plv, cxb);

    // output projection + residual + LN
    hmma1_nt_kernel<<<dim3(DKK / 128, MROWS / 128), 256, 2 * P1_STAGE>>>(cxb, wb + 3ull * 1024 * 1024, bd, x, res, DOUT);
    ln_kernel<<<MROWS, 256>>>(res, gamma, beta, out);
}